// round 2
// baseline (speedup 1.0000x reference)
#include <cuda_runtime.h>
#include <cstdint>

#define B_  64
#define T_  1024
#define U_  512
#define NC_ 1536
#define M_  (B_ * T_)          // 65536
#define NCTA_REC 128
#define SMEM_REC_BYTES 158272  // (24576 + 8192 + 6528 + 272) floats * 4

// ---------------- device scratch (no allocations allowed) ----------------
__device__ float    g_xp[(size_t)M_ * NC_];   // input projections [b*T+t][1536]
__device__ float    g_y [(size_t)M_ * U_];    // layer-0 outputs   [b*T+t][512]
__device__ float    g_h [2][U_ * B_];         // h double buffer   [par][u][b]
__device__ unsigned g_bar;                    // grid barrier counter

// ---------------- f32x2 helpers ----------------
static __device__ __forceinline__ unsigned long long pack2(float x, float y) {
    unsigned long long r;
    asm("mov.b64 %0, {%1, %2};" : "=l"(r) : "f"(x), "f"(y));
    return r;
}
static __device__ __forceinline__ float2 unpack2(unsigned long long v) {
    float2 f;
    asm("mov.b64 {%0, %1}, %2;" : "=f"(f.x), "=f"(f.y) : "l"(v));
    return f;
}
static __device__ __forceinline__ void fma2(unsigned long long& d,
                                            unsigned long long a,
                                            unsigned long long b) {
    asm("fma.rn.f32x2 %0, %1, %2, %0;" : "+l"(d) : "l"(a), "l"(b));
}

// ---------------- init: zero h buffers + barrier ----------------
__global__ void init_kernel() {
    int i = blockIdx.x * blockDim.x + threadIdx.x;
    if (i == 0) g_bar = 0u;
    if (i < 2 * U_ * B_) ((float*)g_h)[i] = 0.0f;
}

// ---------------- GEMM: g_xp[M,1536] = A[M,512] @ W[512,1536] + bias ----------------
// Tiles 128x128x8, 256 threads, microtile 8m x 8n as 4 m-pairs (f32x2).
__global__ __launch_bounds__(256) void gemm_xw(const float* __restrict__ Aext,
                                               int useGY,
                                               const float* __restrict__ W,
                                               const float* __restrict__ bias) {
    const float* A = useGY ? g_y : Aext;
    __shared__ float as[2][8][128];    // A^T tile
    __shared__ float bs2[2][8][256];   // W tile, each value replicated {v,v}

    const int t  = threadIdx.x;
    const int m0 = blockIdx.y * 128;
    const int n0 = blockIdx.x * 128;

    const int ar = t >> 1, ak = (t & 1) * 4;   // A load: row, k-quad
    const int br = t >> 5, bc = (t & 31) * 4;  // W load: k-row, col-quad
    const float* Ap = A + (size_t)(m0 + ar) * U_ + ak;
    const float* Wp = W + (size_t)br * NC_ + n0 + bc;

    const int mr = t >> 4, nr = t & 15;        // compute microtile coords

    unsigned long long acc[4][8];
#pragma unroll
    for (int i = 0; i < 4; i++)
#pragma unroll
        for (int j = 0; j < 8; j++) acc[i][j] = 0ull;

    // prologue: load k-tile 0
    float4 va = *(const float4*)Ap;
    float4 vb = *(const float4*)Wp;
    as[0][ak + 0][ar] = va.x;
    as[0][ak + 1][ar] = va.y;
    as[0][ak + 2][ar] = va.z;
    as[0][ak + 3][ar] = va.w;
    {
        float2* bd = (float2*)&bs2[0][br][bc * 2];
        bd[0] = make_float2(vb.x, vb.x);
        bd[1] = make_float2(vb.y, vb.y);
        bd[2] = make_float2(vb.z, vb.z);
        bd[3] = make_float2(vb.w, vb.w);
    }
    __syncthreads();

    int buf = 0;
    for (int kt = 0; kt < 64; kt++) {
        if (kt < 63) {
            va = *(const float4*)(Ap + (kt + 1) * 8);
            vb = *(const float4*)(Wp + (size_t)(kt + 1) * 8 * NC_);
        }
#pragma unroll
        for (int k = 0; k < 8; k++) {
            ulonglong2 a01 = *(const ulonglong2*)&as[buf][k][mr * 8];
            ulonglong2 a23 = *(const ulonglong2*)&as[buf][k][mr * 8 + 4];
            const ulonglong2* bp = (const ulonglong2*)&bs2[buf][k][nr * 16];
            ulonglong2 b01 = bp[0], b23 = bp[1], b45 = bp[2], b67 = bp[3];
            unsigned long long aa[4] = {a01.x, a01.y, a23.x, a23.y};
            unsigned long long bb[8] = {b01.x, b01.y, b23.x, b23.y,
                                        b45.x, b45.y, b67.x, b67.y};
#pragma unroll
            for (int i = 0; i < 4; i++)
#pragma unroll
                for (int j = 0; j < 8; j++) fma2(acc[i][j], aa[i], bb[j]);
        }
        if (kt < 63) {
            buf ^= 1;
            as[buf][ak + 0][ar] = va.x;
            as[buf][ak + 1][ar] = va.y;
            as[buf][ak + 2][ar] = va.z;
            as[buf][ak + 3][ar] = va.w;
            float2* bd = (float2*)&bs2[buf][br][bc * 2];
            bd[0] = make_float2(vb.x, vb.x);
            bd[1] = make_float2(vb.y, vb.y);
            bd[2] = make_float2(vb.z, vb.z);
            bd[3] = make_float2(vb.w, vb.w);
            __syncthreads();
        }
    }

    // epilogue: add bias, write g_xp
    float bv[8];
#pragma unroll
    for (int j = 0; j < 8; j++) bv[j] = bias[n0 + nr * 8 + j];
    float* Cp = g_xp + (size_t)(m0 + mr * 8) * NC_ + n0 + nr * 8;
#pragma unroll
    for (int r = 0; r < 8; r++) {
        float v[8];
#pragma unroll
        for (int j = 0; j < 8; j++) {
            float2 f = unpack2(acc[r >> 1][j]);
            v[j] = (r & 1) ? f.y : f.x;
        }
        float4 o0 = make_float4(v[0] + bv[0], v[1] + bv[1], v[2] + bv[2], v[3] + bv[3]);
        float4 o1 = make_float4(v[4] + bv[4], v[5] + bv[5], v[6] + bv[6], v[7] + bv[7]);
        *(float4*)(Cp + (size_t)r * NC_)     = o0;
        *(float4*)(Cp + (size_t)r * NC_ + 4) = o1;
    }
}

// ---------------- persistent GRU recurrence ----------------
// 128 CTAs (1/SM, all resident) x 256 threads. CTA tile: 16 batches x 16 units.
// 8 warps split K=512 (64 each); warp microtile 4b x 2u x 3 gates in f32x2.
__global__ __launch_bounds__(256) void gru_rec(const float* __restrict__ R,
                                               const float* __restrict__ bvec, // [2][1536]
                                               float* __restrict__ yext, int writeGY,
                                               float* __restrict__ hlast) {
    extern __shared__ float sm[];
    float* Rs  = sm;                        // [3][512][16]       24576 floats
    float* hs  = Rs + 3 * 512 * 16;         // [512][16] (k,b)     8192
    float* red = hs + 512 * 16;             // [8][3][16][17]      6528
    float* hso = red + 8 * 3 * 16 * 17;     // [16][17]            272
    float* yv  = writeGY ? g_y : yext;

    const int tid = threadIdx.x;
    const int bid = blockIdx.x;
    const int bg = bid >> 5, ug = bid & 31;
    const int b_base = bg * 16, u_base = ug * 16;

    // one-time: load this CTA's R slab (48 columns) into smem
    for (int i = tid; i < 3 * 512 * 16; i += 256) {
        int g = i >> 13;
        int rem = i & 8191;
        int k = rem >> 4, j = rem & 15;
        Rs[i] = R[(size_t)k * NC_ + g * U_ + u_base + j];
    }

    // owner identity: one (b,u) output element per thread
    const int b_loc = tid >> 4, u_loc = tid & 15;
    const int b_glob = b_base + b_loc, u_glob = u_base + u_loc;
    const float bz  = bvec[NC_ + u_glob];
    const float brr = bvec[NC_ + U_ + u_glob];
    const float bhh = bvec[NC_ + 2 * U_ + u_glob];
    const float* xpp = g_xp + (size_t)b_glob * T_ * NC_;
    float* yrow = yv + (size_t)b_glob * T_ * U_ + u_glob;

    // warp k-slice + microtile coords
    const int w = tid >> 5, l = tid & 31;
    const int kbase = w * 64;
    const int bq = (l & 3) * 4;        // 4 batches (2 f32x2 pairs)
    const int uq = (l >> 2) * 2;       // 2 units

    __syncthreads();  // Rs ready

    for (int t = 0; t < T_; t++) {
        const int par = t & 1;
        const float* hg = g_h[par];
        // load h tile [512 u][16 b] via L2 (bypass stale L1)
#pragma unroll
        for (int i = 0; i < 8; i++) {
            int idx = tid + i * 256;
            int u = idx >> 2, q = (idx & 3) * 4;
            float4 v = __ldcg((const float4*)(hg + u * B_ + b_base + q));
            *(float4*)&hs[u * 16 + q] = v;
        }
        // prefetch this thread's x projections
        float xz = __ldg(xpp + (size_t)t * NC_ + u_glob);
        float xr = __ldg(xpp + (size_t)t * NC_ + U_ + u_glob);
        float xh = __ldg(xpp + (size_t)t * NC_ + 2 * U_ + u_glob);
        __syncthreads();

        unsigned long long acc[3][2][2];
#pragma unroll
        for (int g = 0; g < 3; g++)
#pragma unroll
            for (int p = 0; p < 2; p++)
#pragma unroll
                for (int j = 0; j < 2; j++) acc[g][p][j] = 0ull;

#pragma unroll 4
        for (int kk = 0; kk < 64; kk++) {
            int k = kbase + kk;
            ulonglong2 hp = *(const ulonglong2*)&hs[k * 16 + bq];
#pragma unroll
            for (int g = 0; g < 3; g++) {
                float2 rv = *(const float2*)&Rs[g * 8192 + k * 16 + uq];
                unsigned long long r0 = pack2(rv.x, rv.x);
                unsigned long long r1 = pack2(rv.y, rv.y);
                fma2(acc[g][0][0], hp.x, r0);
                fma2(acc[g][1][0], hp.y, r0);
                fma2(acc[g][0][1], hp.x, r1);
                fma2(acc[g][1][1], hp.y, r1);
            }
        }

        // write partials
#pragma unroll
        for (int g = 0; g < 3; g++) {
            int base = (w * 3 + g) * 16;
#pragma unroll
            for (int p = 0; p < 2; p++)
#pragma unroll
                for (int j = 0; j < 2; j++) {
                    float2 f = unpack2(acc[g][p][j]);
                    red[(base + bq + 2 * p)     * 17 + uq + j] = f.x;
                    red[(base + bq + 2 * p + 1) * 17 + uq + j] = f.y;
                }
        }
        __syncthreads();

        // owner: reduce across 8 warps, apply gates
        float s0 = 0.f, s1 = 0.f, s2 = 0.f;
#pragma unroll
        for (int ww = 0; ww < 8; ww++) {
            s0 += red[((ww * 3 + 0) * 16 + b_loc) * 17 + u_loc];
            s1 += red[((ww * 3 + 1) * 16 + b_loc) * 17 + u_loc];
            s2 += red[((ww * 3 + 2) * 16 + b_loc) * 17 + u_loc];
        }
        float hold = hs[u_glob * 16 + b_loc];
        float z  = 1.0f / (1.0f + expf(-(xz + s0 + bz)));
        float r  = 1.0f / (1.0f + expf(-(xr + s1 + brr)));
        float hh = tanhf(xh + r * (s2 + bhh));
        float hn = z * hold + (1.0f - z) * hh;

        yrow[(size_t)t * U_] = hn;
        if (t == T_ - 1) hlast[b_glob * U_ + u_glob] = hn;
        hso[b_loc * 17 + u_loc] = hn;
        __syncthreads();

        // coalesced h store to the other global buffer (u-major)
        {
            int u2 = tid >> 4, b2 = tid & 15;
            float v = hso[b2 * 17 + u2];
            __stcg((float*)g_h[1 - par] + (u_base + u2) * B_ + b_base + b2, v);
        }
        __threadfence();
        __syncthreads();
        if (tid == 0) {
            atomicAdd(&g_bar, 1u);
            unsigned target = (unsigned)NCTA_REC * (unsigned)(t + 1);
            while (atomicAdd(&g_bar, 0u) < target) __nanosleep(64);
        }
        __syncthreads();
    }
}

// ---------------- launcher ----------------
extern "C" void kernel_launch(void* const* d_in, const int* in_sizes, int n_in,
                              void* d_out, int out_size) {
    const float* x  = (const float*)d_in[0];
    const float* W0 = (const float*)d_in[1];
    const float* R0 = (const float*)d_in[2];
    const float* b0 = (const float*)d_in[3];
    const float* W1 = (const float*)d_in[4];
    const float* R1 = (const float*)d_in[5];
    const float* b1 = (const float*)d_in[6];

    float* out  = (float*)d_out;
    float* out1 = out;                               // [64,1024,512]
    float* h0   = out + (size_t)B_ * T_ * U_;        // [64,512]
    float* h1   = h0 + (size_t)B_ * U_;              // [64,512]

    cudaFuncSetAttribute(gru_rec, cudaFuncAttributeMaxDynamicSharedMemorySize,
                         SMEM_REC_BYTES);

    dim3 gg(12, 512);
    // layer 0
    init_kernel<<<256, 256>>>();
    gemm_xw<<<gg, 256>>>(x, 0, W0, b0);
    gru_rec<<<NCTA_REC, 256, SMEM_REC_BYTES>>>(R0, b0, nullptr, 1, h0);
    // layer 1
    init_kernel<<<256, 256>>>();
    gemm_xw<<<gg, 256>>>(nullptr, 1, W1, b1);
    gru_rec<<<NCTA_REC, 256, SMEM_REC_BYTES>>>(R1, b1, out1, 0, h1);
}

// round 3
// speedup vs baseline: 1.6348x; 1.6348x over previous
#include <cuda_runtime.h>
#include <cstdint>

#define B_  64
#define T_  1024
#define U_  512
#define NC_ 1536
#define M_  (B_ * T_)          // 65536
#define NCTA_REC 128
#define SMEM_REC_BYTES 158272  // (24576 + 8192 + 6528 + 272) floats * 4

// ---------------- device scratch (no allocations allowed) ----------------
__device__ float    g_xp[(size_t)M_ * NC_];   // input projections [b*T+t][1536]
__device__ float    g_y [(size_t)M_ * U_];    // layer-0 outputs   [b*T+t][512]
__device__ float    g_h [2][U_ * B_];         // h double buffer   [par][u][b]
__device__ unsigned g_bar;                    // grid barrier counter

// ---------------- f32x2 helpers ----------------
static __device__ __forceinline__ unsigned long long pack2(float x, float y) {
    unsigned long long r;
    asm("mov.b64 %0, {%1, %2};" : "=l"(r) : "f"(x), "f"(y));
    return r;
}
static __device__ __forceinline__ float2 unpack2(unsigned long long v) {
    float2 f;
    asm("mov.b64 {%0, %1}, %2;" : "=f"(f.x), "=f"(f.y) : "l"(v));
    return f;
}
static __device__ __forceinline__ void fma2(unsigned long long& d,
                                            unsigned long long a,
                                            unsigned long long b) {
    asm("fma.rn.f32x2 %0, %1, %2, %0;" : "+l"(d) : "l"(a), "l"(b));
}
static __device__ __forceinline__ float fsig(float x) {
    return __fdividef(1.0f, 1.0f + __expf(-x));
}
static __device__ __forceinline__ float ftanh(float x) {
    // tanh(x) = 1 - 2/(exp(2x)+1); robust at both tails with __expf
    return 1.0f - __fdividef(2.0f, __expf(2.0f * x) + 1.0f);
}

// ---------------- tiny init: reset grid barrier ----------------
__global__ void init_bar() { g_bar = 0u; }

// ---------------- GEMM: g_xp[M,1536] = A[M,512] @ W[512,1536] + bias ----------------
// Tiles 128x128x8, 256 threads. Microtile 8m x 8n as 8 m-rows x 4 n-pairs (f32x2).
// B tile stored unreplicated; a-dups packed on the alu pipe (hidden under fma window).
__global__ __launch_bounds__(256) void gemm_xw(const float* __restrict__ Aext,
                                               int useGY,
                                               const float* __restrict__ W,
                                               const float* __restrict__ bias) {
    const float* A = useGY ? g_y : Aext;
    __shared__ float as[2][8][128];   // A^T tile
    __shared__ float bs[2][8][128];   // W tile (unreplicated)

    const int t  = threadIdx.x;
    const int m0 = blockIdx.y * 128;
    const int n0 = blockIdx.x * 128;

    const int ar = t >> 1, ak = (t & 1) * 4;   // A load: row, k-quad
    const int br = t >> 5, bc = (t & 31) * 4;  // W load: k-row, col-quad
    const float* Ap = A + (size_t)(m0 + ar) * U_ + ak;
    const float* Wp = W + (size_t)br * NC_ + n0 + bc;

    const int mr = t >> 4, nr = t & 15;        // compute microtile coords

    unsigned long long acc[8][4];
#pragma unroll
    for (int i = 0; i < 8; i++)
#pragma unroll
        for (int j = 0; j < 4; j++) acc[i][j] = 0ull;

    // prologue: k-tile 0
    float4 va = *(const float4*)Ap;
    float4 vb = *(const float4*)Wp;
    as[0][ak + 0][ar] = va.x;
    as[0][ak + 1][ar] = va.y;
    as[0][ak + 2][ar] = va.z;
    as[0][ak + 3][ar] = va.w;
    *(float4*)&bs[0][br][bc] = vb;
    __syncthreads();

    int buf = 0;
    for (int kt = 0; kt < 64; kt++) {
        if (kt < 63) {
            va = *(const float4*)(Ap + (kt + 1) * 8);
            vb = *(const float4*)(Wp + (size_t)(kt + 1) * 8 * NC_);
        }
#pragma unroll
        for (int k = 0; k < 8; k++) {
            float4 a0 = *(const float4*)&as[buf][k][mr * 8];
            float4 a1 = *(const float4*)&as[buf][k][mr * 8 + 4];
            ulonglong2 b01 = *(const ulonglong2*)&bs[buf][k][nr * 8];
            ulonglong2 b23 = *(const ulonglong2*)&bs[buf][k][nr * 8 + 4];
            unsigned long long aa[8];
            aa[0] = pack2(a0.x, a0.x); aa[1] = pack2(a0.y, a0.y);
            aa[2] = pack2(a0.z, a0.z); aa[3] = pack2(a0.w, a0.w);
            aa[4] = pack2(a1.x, a1.x); aa[5] = pack2(a1.y, a1.y);
            aa[6] = pack2(a1.z, a1.z); aa[7] = pack2(a1.w, a1.w);
            unsigned long long bb[4] = {b01.x, b01.y, b23.x, b23.y};
#pragma unroll
            for (int i = 0; i < 8; i++)
#pragma unroll
                for (int j = 0; j < 4; j++) fma2(acc[i][j], aa[i], bb[j]);
        }
        if (kt < 63) {
            buf ^= 1;
            as[buf][ak + 0][ar] = va.x;
            as[buf][ak + 1][ar] = va.y;
            as[buf][ak + 2][ar] = va.z;
            as[buf][ak + 3][ar] = va.w;
            *(float4*)&bs[buf][br][bc] = vb;
            __syncthreads();
        }
    }

    // epilogue: add bias, write g_xp (n-pairs are contiguous)
    float bv[8];
#pragma unroll
    for (int j = 0; j < 8; j++) bv[j] = bias[n0 + nr * 8 + j];
    float* Cp = g_xp + (size_t)(m0 + mr * 8) * NC_ + n0 + nr * 8;
#pragma unroll
    for (int i = 0; i < 8; i++) {
        float2 f0 = unpack2(acc[i][0]);
        float2 f1 = unpack2(acc[i][1]);
        float2 f2 = unpack2(acc[i][2]);
        float2 f3 = unpack2(acc[i][3]);
        float4 o0 = make_float4(f0.x + bv[0], f0.y + bv[1], f1.x + bv[2], f1.y + bv[3]);
        float4 o1 = make_float4(f2.x + bv[4], f2.y + bv[5], f3.x + bv[6], f3.y + bv[7]);
        *(float4*)(Cp + (size_t)i * NC_)     = o0;
        *(float4*)(Cp + (size_t)i * NC_ + 4) = o1;
    }
}

// ---------------- persistent GRU recurrence ----------------
// 128 CTAs (1/SM, all resident) x 256 threads. CTA tile: 16 batches x 16 units.
// 8 warps split K=512 (64 each); warp microtile 4b x 1 u-pair x 3 gates (f32x2).
__global__ __launch_bounds__(256) void gru_rec(const float* __restrict__ R,
                                               const float* __restrict__ bvec, // [2][1536]
                                               float* __restrict__ yext, int writeGY,
                                               float* __restrict__ hlast) {
    extern __shared__ float sm[];
    float* Rs  = sm;                        // [3][512][16]       24576 floats
    float* hs  = Rs + 3 * 512 * 16;         // [512][16] (k,b)     8192
    float* red = hs + 512 * 16;             // [8][3][16][17]      6528
    float* hso = red + 8 * 3 * 16 * 17;     // [16][17]            272
    float* yv  = writeGY ? g_y : yext;

    const int tid = threadIdx.x;
    const int bid = blockIdx.x;
    const int bg = bid >> 5, ug = bid & 31;
    const int b_base = bg * 16, u_base = ug * 16;

    // one-time: load this CTA's R slab (48 columns) into smem
    for (int i = tid; i < 3 * 512 * 16; i += 256) {
        int g = i >> 13;
        int rem = i & 8191;
        int k = rem >> 4, j = rem & 15;
        Rs[i] = R[(size_t)k * NC_ + g * U_ + u_base + j];
    }

    // owner identity: one (b,u) output element per thread
    const int b_loc = tid >> 4, u_loc = tid & 15;
    const int b_glob = b_base + b_loc, u_glob = u_base + u_loc;
    const float bz  = bvec[NC_ + u_glob];
    const float brr = bvec[NC_ + U_ + u_glob];
    const float bhh = bvec[NC_ + 2 * U_ + u_glob];
    const float* xpp = g_xp + (size_t)b_glob * T_ * NC_;
    float* yrow = yv + (size_t)b_glob * T_ * U_ + u_glob;

    // warp k-slice + microtile coords
    const int w = tid >> 5, l = tid & 31;
    const int kbase = w * 64;
    const int bq = (l & 3) * 4;        // 4 batches
    const int uq = (l >> 2) * 2;       // 1 u-pair (2 units)

    __syncthreads();  // Rs ready

    volatile unsigned* barp = &g_bar;

    for (int t = 0; t < T_; t++) {
        const int par = t & 1;
        if (t == 0) {
            // h0 = 0: zero the smem h tile, no global read
#pragma unroll
            for (int i = 0; i < 8; i++) {
                int idx = tid + i * 256;
                *(float4*)&hs[idx * 4] = make_float4(0.f, 0.f, 0.f, 0.f);
            }
        } else {
            const float* hg = g_h[par];
#pragma unroll
            for (int i = 0; i < 8; i++) {
                int idx = tid + i * 256;
                int u = idx >> 2, q = (idx & 3) * 4;
                float4 v = __ldcg((const float4*)(hg + u * B_ + b_base + q));
                *(float4*)&hs[u * 16 + q] = v;
            }
        }
        // prefetch this thread's x projections
        float xz = __ldg(xpp + (size_t)t * NC_ + u_glob);
        float xr = __ldg(xpp + (size_t)t * NC_ + U_ + u_glob);
        float xh = __ldg(xpp + (size_t)t * NC_ + 2 * U_ + u_glob);
        __syncthreads();

        unsigned long long acc[4][3];
#pragma unroll
        for (int i = 0; i < 4; i++)
#pragma unroll
            for (int g = 0; g < 3; g++) acc[i][g] = 0ull;

#pragma unroll 4
        for (int kk = 0; kk < 64; kk++) {
            int k = kbase + kk;
            float4 h4 = *(const float4*)&hs[k * 16 + bq];
            unsigned long long hh0 = pack2(h4.x, h4.x);
            unsigned long long hh1 = pack2(h4.y, h4.y);
            unsigned long long hh2 = pack2(h4.z, h4.z);
            unsigned long long hh3 = pack2(h4.w, h4.w);
#pragma unroll
            for (int g = 0; g < 3; g++) {
                unsigned long long rp = *(const unsigned long long*)&Rs[g * 8192 + k * 16 + uq];
                fma2(acc[0][g], hh0, rp);
                fma2(acc[1][g], hh1, rp);
                fma2(acc[2][g], hh2, rp);
                fma2(acc[3][g], hh3, rp);
            }
        }

        // write partials: red[w][g][b][u]
#pragma unroll
        for (int g = 0; g < 3; g++) {
            int base = (w * 3 + g) * 16;
#pragma unroll
            for (int i = 0; i < 4; i++) {
                float2 f = unpack2(acc[i][g]);
                red[(base + bq + i) * 17 + uq]     = f.x;
                red[(base + bq + i) * 17 + uq + 1] = f.y;
            }
        }
        __syncthreads();

        // owner: reduce across 8 warps, apply gates
        float s0 = 0.f, s1 = 0.f, s2 = 0.f;
#pragma unroll
        for (int ww = 0; ww < 8; ww++) {
            s0 += red[((ww * 3 + 0) * 16 + b_loc) * 17 + u_loc];
            s1 += red[((ww * 3 + 1) * 16 + b_loc) * 17 + u_loc];
            s2 += red[((ww * 3 + 2) * 16 + b_loc) * 17 + u_loc];
        }
        float hold = hs[u_glob * 16 + b_loc - u_base * 16]; // hs indexed by local u
        // NOTE: hs is [512 global k][16 b]; the owner's unit row is global u_glob
        hold = hs[u_glob * 16 + b_loc];
        float z  = fsig(xz + s0 + bz);
        float r  = fsig(xr + s1 + brr);
        float hh = ftanh(xh + r * (s2 + bhh));
        float hn = z * hold + (1.0f - z) * hh;

        yrow[(size_t)t * U_] = hn;

        if (t == T_ - 1) {
            hlast[b_glob * U_ + u_glob] = hn;
        } else {
            hso[b_loc * 17 + u_loc] = hn;
            __syncthreads();
            // coalesced h store to the other global buffer (u-major)
            {
                int u2 = tid >> 4, b2 = tid & 15;
                float v = hso[b2 * 17 + u2];
                __stcg((float*)g_h[1 - par] + (u_base + u2) * B_ + b_base + b2, v);
            }
            __threadfence();
            __syncthreads();
            if (tid == 0) {
                atomicAdd(&g_bar, 1u);
                unsigned target = (unsigned)NCTA_REC * (unsigned)(t + 1);
                while (*barp < target) { }
            }
            __syncthreads();
        }
    }
}

// ---------------- launcher ----------------
extern "C" void kernel_launch(void* const* d_in, const int* in_sizes, int n_in,
                              void* d_out, int out_size) {
    const float* x  = (const float*)d_in[0];
    const float* W0 = (const float*)d_in[1];
    const float* R0 = (const float*)d_in[2];
    const float* b0 = (const float*)d_in[3];
    const float* W1 = (const float*)d_in[4];
    const float* R1 = (const float*)d_in[5];
    const float* b1 = (const float*)d_in[6];

    float* out  = (float*)d_out;
    float* out1 = out;                               // [64,1024,512]
    float* h0   = out + (size_t)B_ * T_ * U_;        // [64,512]
    float* h1   = h0 + (size_t)B_ * U_;              // [64,512]

    cudaFuncSetAttribute(gru_rec, cudaFuncAttributeMaxDynamicSharedMemorySize,
                         SMEM_REC_BYTES);

    dim3 gg(12, 512);
    // layer 0
    gemm_xw<<<gg, 256>>>(x, 0, W0, b0);
    init_bar<<<1, 32>>>();
    gru_rec<<<NCTA_REC, 256, SMEM_REC_BYTES>>>(R0, b0, nullptr, 1, h0);
    // layer 1
    gemm_xw<<<gg, 256>>>(nullptr, 1, W1, b1);
    init_bar<<<1, 32>>>();
    gru_rec<<<NCTA_REC, 256, SMEM_REC_BYTES>>>(R1, b1, out1, 0, h1);
}

// round 5
// speedup vs baseline: 1.8764x; 1.1477x over previous
#include <cuda_runtime.h>
#include <cuda_bf16.h>
#include <cstdint>

#define B_  64
#define T_  1024
#define U_  512
#define NC_ 1536
#define M_  (B_ * T_)          // 65536
#define NCTA_REC 128
#define SMEM_REC_BYTES 158272
#define SMEM_GEMM_B 82432      // 2 stages * 40960 + 512 bias

// ---------------- device scratch ----------------
__device__ float    g_xp[(size_t)M_ * NC_];       // input projections
__device__ float    g_h [2][U_ * B_];             // h double buffer [par][u][b]
__device__ unsigned g_bar;
__device__ __nv_bfloat16 g_ah[(size_t)M_ * U_];   // A hi (bf16 split) [m][k]
__device__ __nv_bfloat16 g_al[(size_t)M_ * U_];   // A lo
__device__ __nv_bfloat16 g_wh[(size_t)NC_ * U_];  // W^T hi [n][k]
__device__ __nv_bfloat16 g_wl[(size_t)NC_ * U_];  // W^T lo

// ---------------- f32x2 helpers (recurrence) ----------------
static __device__ __forceinline__ unsigned long long pack2(float x, float y) {
    unsigned long long r;
    asm("mov.b64 %0, {%1, %2};" : "=l"(r) : "f"(x), "f"(y));
    return r;
}
static __device__ __forceinline__ float2 unpack2(unsigned long long v) {
    float2 f;
    asm("mov.b64 {%0, %1}, %2;" : "=f"(f.x), "=f"(f.y) : "l"(v));
    return f;
}
static __device__ __forceinline__ void fma2(unsigned long long& d,
                                            unsigned long long a,
                                            unsigned long long b) {
    asm("fma.rn.f32x2 %0, %1, %2, %0;" : "+l"(d) : "l"(a), "l"(b));
}
static __device__ __forceinline__ float fsig(float x) {
    return __fdividef(1.0f, 1.0f + __expf(-x));
}
static __device__ __forceinline__ float ftanh(float x) {
    return 1.0f - __fdividef(2.0f, __expf(2.0f * x) + 1.0f);
}

// ---------------- mma / ldmatrix / cp.async helpers ----------------
static __device__ __forceinline__ uint32_t smem_u32(const void* p) {
    uint32_t a;
    asm("{ .reg .u64 t; cvta.to.shared.u64 t, %1; cvt.u32.u64 %0, t; }"
        : "=r"(a) : "l"(p));
    return a;
}
#define LDSM4(r, addr) \
    asm volatile("ldmatrix.sync.aligned.m8n8.x4.shared.b16 {%0,%1,%2,%3}, [%4];" \
        : "=r"((r)[0]), "=r"((r)[1]), "=r"((r)[2]), "=r"((r)[3]) : "r"(addr))
#define MMA_BF16(d, a, b0v, b1v) \
    asm volatile("mma.sync.aligned.m16n8k16.row.col.f32.bf16.bf16.f32 " \
        "{%0,%1,%2,%3}, {%4,%5,%6,%7}, {%8,%9}, {%0,%1,%2,%3};" \
        : "+f"((d)[0]), "+f"((d)[1]), "+f"((d)[2]), "+f"((d)[3]) \
        : "r"((a)[0]), "r"((a)[1]), "r"((a)[2]), "r"((a)[3]), "r"(b0v), "r"(b1v))
#define CPA16(dst, src) \
    asm volatile("cp.async.cg.shared.global [%0], [%1], 16;" :: "r"(dst), "l"(src))
#define CPA_COMMIT() asm volatile("cp.async.commit_group;")
#define CPA_WAIT0()  asm volatile("cp.async.wait_group 0;" ::: "memory")

// ---------------- init barrier ----------------
__global__ void init_bar() { g_bar = 0u; }

// ---------------- split kernels (fp32 -> bf16 hi/lo) ----------------
__global__ void split_x(const float* __restrict__ src) {
    size_t n = (size_t)M_ * U_;
    for (size_t i = (size_t)blockIdx.x * blockDim.x + threadIdx.x; i < n;
         i += (size_t)gridDim.x * blockDim.x) {
        float v = src[i];
        __nv_bfloat16 h = __float2bfloat16(v);
        g_ah[i] = h;
        g_al[i] = __float2bfloat16(v - __bfloat162float(h));
    }
}
__global__ void split_w(const float* __restrict__ W) {
    int idx = blockIdx.x * blockDim.x + threadIdx.x;   // out [n][k]
    if (idx < NC_ * U_) {
        int n = idx / U_, k = idx - n * U_;
        float v = W[(size_t)k * NC_ + n];
        __nv_bfloat16 h = __float2bfloat16(v);
        g_wh[idx] = h;
        g_wl[idx] = __float2bfloat16(v - __bfloat162float(h));
    }
}

// ---------------- tensor-core GEMM via mma.sync: g_xp = A @ W^T + bias ----------------
// CTA 128m x 128n. 8 warps = 4m x 2n, warp tile 32x64. K in 16 tiles of 32.
// 3-pass bf16 split fused per k-step. smem stage: Ah,Al,Bh,Bl each 128x(32+8pad) halfs.
__global__ __launch_bounds__(256) void gemm_mma(const float* __restrict__ bias) {
    extern __shared__ char sm[];
    const uint32_t sb = smem_u32(sm);
    float* bias_s = (float*)(sm + 81920);

    const int tid = threadIdx.x, lane = tid & 31, wid = tid >> 5;
    const int wm = wid >> 1, wn = wid & 1;
    const int m0 = blockIdx.y * 128, n0 = blockIdx.x * 128;

    if (tid < 128) bias_s[tid] = bias[n0 + tid];

    // loader: k-tile kt -> stage (4 matrices, 16B per cp.async)
    const int lrow = tid >> 2, lch = tid & 3;              // 2 chunks/thread/matrix
    auto load_tile = [&](int kt, int stage) {
#pragma unroll
        for (int i = 0; i < 2; i++) {
            int row = lrow + i * 64;
            size_t go = (size_t)row * U_ + kt * 32 + lch * 8;   // halfs
            uint32_t so = sb + stage * 40960 + row * 80 + lch * 16;
            CPA16(so,         (const char*)g_ah + 2 * ((size_t)m0 * U_ + go));
            CPA16(so + 10240, (const char*)g_al + 2 * ((size_t)m0 * U_ + go));
            CPA16(so + 20480, (const char*)g_wh + 2 * ((size_t)n0 * U_ + go));
            CPA16(so + 30720, (const char*)g_wl + 2 * ((size_t)n0 * U_ + go));
        }
        CPA_COMMIT();
    };

    float acc[2][8][4];
#pragma unroll
    for (int f = 0; f < 2; f++)
#pragma unroll
        for (int j = 0; j < 8; j++)
#pragma unroll
            for (int c = 0; c < 4; c++) acc[f][j][c] = 0.f;

    // ldmatrix lane-address offsets (bytes within a matrix region)
    const uint32_t aoff = (uint32_t)((wm * 32 + (lane & 15)) * 80 + ((lane >> 4) * 8) * 2);
    const uint32_t boff = (uint32_t)((wn * 64 + (lane & 7) + ((lane >> 4) & 1) * 8) * 80
                                     + (((lane >> 3) & 1) * 8) * 2);

    load_tile(0, 0);
    CPA_WAIT0();
    __syncthreads();

    int buf = 0;
#pragma unroll 1
    for (int kt = 0; kt < 16; kt++) {
        if (kt < 15) load_tile(kt + 1, buf ^ 1);
        const uint32_t sbase = sb + buf * 40960;
#pragma unroll
        for (int ks = 0; ks < 2; ks++) {
            const uint32_t kb = (uint32_t)(ks * 16 * 2);   // byte offset of k-step
            uint32_t ah[2][4], al[2][4], bh[4][4], bl[4][4];
            LDSM4(ah[0], sbase + aoff + kb);
            LDSM4(ah[1], sbase + aoff + kb + 16 * 80);
            LDSM4(al[0], sbase + 10240 + aoff + kb);
            LDSM4(al[1], sbase + 10240 + aoff + kb + 16 * 80);
#pragma unroll
            for (int p = 0; p < 4; p++) {
                LDSM4(bh[p], sbase + 20480 + boff + kb + p * 16 * 80);
                LDSM4(bl[p], sbase + 30720 + boff + kb + p * 16 * 80);
            }
#pragma unroll
            for (int f = 0; f < 2; f++)
#pragma unroll
                for (int j = 0; j < 8; j++) {
                    uint32_t bh0 = bh[j >> 1][(j & 1) * 2], bh1 = bh[j >> 1][(j & 1) * 2 + 1];
                    uint32_t bl0 = bl[j >> 1][(j & 1) * 2], bl1 = bl[j >> 1][(j & 1) * 2 + 1];
                    MMA_BF16(acc[f][j], ah[f], bh0, bh1);
                    MMA_BF16(acc[f][j], ah[f], bl0, bl1);
                    MMA_BF16(acc[f][j], al[f], bh0, bh1);
                }
        }
        if (kt < 15) {
            CPA_WAIT0();
            __syncthreads();
            buf ^= 1;
        }
    }

    // epilogue: add bias, write g_xp
#pragma unroll
    for (int f = 0; f < 2; f++) {
        const int r0 = m0 + wm * 32 + f * 16 + (lane >> 2);
#pragma unroll
        for (int j = 0; j < 8; j++) {
            const int cl = wn * 64 + j * 8 + (lane & 3) * 2;
            const int cg = n0 + cl;
            float2 o0 = make_float2(acc[f][j][0] + bias_s[cl], acc[f][j][1] + bias_s[cl + 1]);
            float2 o1 = make_float2(acc[f][j][2] + bias_s[cl], acc[f][j][3] + bias_s[cl + 1]);
            *(float2*)(g_xp + (size_t)r0 * NC_ + cg)       = o0;
            *(float2*)(g_xp + (size_t)(r0 + 8) * NC_ + cg) = o1;
        }
    }
}

// ---------------- persistent GRU recurrence ----------------
// writeSplit=1: emit bf16 hi/lo into g_ah/g_al (feeds next layer's GEMM directly).
__global__ __launch_bounds__(256) void gru_rec(const float* __restrict__ R,
                                               const float* __restrict__ bvec,
                                               float* __restrict__ yext, int writeSplit,
                                               float* __restrict__ hlast) {
    extern __shared__ float smf[];
    float* Rs  = smf;                       // [3][512][16]
    float* hs  = Rs + 3 * 512 * 16;         // [512][16]
    float* red = hs + 512 * 16;             // [8][3][16][17]
    float* hso = red + 8 * 3 * 16 * 17;     // [16][17]

    const int tid = threadIdx.x;
    const int bid = blockIdx.x;
    const int bg = bid >> 5, ug = bid & 31;
    const int b_base = bg * 16, u_base = ug * 16;

    for (int i = tid; i < 3 * 512 * 16; i += 256) {
        int g = i >> 13;
        int rem = i & 8191;
        int k = rem >> 4, j = rem & 15;
        Rs[i] = R[(size_t)k * NC_ + g * U_ + u_base + j];
    }

    const int b_loc = tid >> 4, u_loc = tid & 15;
    const int b_glob = b_base + b_loc, u_glob = u_base + u_loc;
    const float bz  = bvec[NC_ + u_glob];
    const float brr = bvec[NC_ + U_ + u_glob];
    const float bhh = bvec[NC_ + 2 * U_ + u_glob];
    const float* xpp = g_xp + (size_t)b_glob * T_ * NC_;
    const size_t orow = (size_t)b_glob * T_ * U_ + u_glob;

    const int w = tid >> 5, l = tid & 31;
    const int kbase = w * 64;
    const int bq = (l & 3) * 4;
    const int uq = (l >> 2) * 2;

    __syncthreads();

    volatile unsigned* barp = &g_bar;

    for (int t = 0; t < T_; t++) {
        const int par = t & 1;
        if (t == 0) {
#pragma unroll
            for (int i = 0; i < 8; i++) {
                int idx = tid + i * 256;
                *(float4*)&hs[idx * 4] = make_float4(0.f, 0.f, 0.f, 0.f);
            }
        } else {
            const float* hg = g_h[par];
#pragma unroll
            for (int i = 0; i < 8; i++) {
                int idx = tid + i * 256;
                int u = idx >> 2, q = (idx & 3) * 4;
                float4 v = __ldcg((const float4*)(hg + u * B_ + b_base + q));
                *(float4*)&hs[u * 16 + q] = v;
            }
        }
        float xz = __ldg(xpp + (size_t)t * NC_ + u_glob);
        float xr = __ldg(xpp + (size_t)t * NC_ + U_ + u_glob);
        float xh = __ldg(xpp + (size_t)t * NC_ + 2 * U_ + u_glob);
        __syncthreads();

        unsigned long long acc[4][3];
#pragma unroll
        for (int i = 0; i < 4; i++)
#pragma unroll
            for (int g = 0; g < 3; g++) acc[i][g] = 0ull;

#pragma unroll 4
        for (int kk = 0; kk < 64; kk++) {
            int k = kbase + kk;
            float4 h4 = *(const float4*)&hs[k * 16 + bq];
            unsigned long long hh0 = pack2(h4.x, h4.x);
            unsigned long long hh1 = pack2(h4.y, h4.y);
            unsigned long long hh2 = pack2(h4.z, h4.z);
            unsigned long long hh3 = pack2(h4.w, h4.w);
#pragma unroll
            for (int g = 0; g < 3; g++) {
                unsigned long long rp = *(const unsigned long long*)&Rs[g * 8192 + k * 16 + uq];
                fma2(acc[0][g], hh0, rp);
                fma2(acc[1][g], hh1, rp);
                fma2(acc[2][g], hh2, rp);
                fma2(acc[3][g], hh3, rp);
            }
        }

#pragma unroll
        for (int g = 0; g < 3; g++) {
            int base = (w * 3 + g) * 16;
#pragma unroll
            for (int i = 0; i < 4; i++) {
                float2 f = unpack2(acc[i][g]);
                red[(base + bq + i) * 17 + uq]     = f.x;
                red[(base + bq + i) * 17 + uq + 1] = f.y;
            }
        }
        __syncthreads();

        float s0 = 0.f, s1 = 0.f, s2 = 0.f;
#pragma unroll
        for (int ww = 0; ww < 8; ww++) {
            s0 += red[((ww * 3 + 0) * 16 + b_loc) * 17 + u_loc];
            s1 += red[((ww * 3 + 1) * 16 + b_loc) * 17 + u_loc];
            s2 += red[((ww * 3 + 2) * 16 + b_loc) * 17 + u_loc];
        }
        float hold = hs[u_glob * 16 + b_loc];
        float z  = fsig(xz + s0 + bz);
        float r  = fsig(xr + s1 + brr);
        float hh = ftanh(xh + r * (s2 + bhh));
        float hn = z * hold + (1.0f - z) * hh;

        if (writeSplit) {
            __nv_bfloat16 hi = __float2bfloat16(hn);
            g_ah[orow + (size_t)t * U_] = hi;
            g_al[orow + (size_t)t * U_] = __float2bfloat16(hn - __bfloat162float(hi));
        } else {
            yext[orow + (size_t)t * U_] = hn;
        }

        if (t == T_ - 1) {
            hlast[b_glob * U_ + u_glob] = hn;
        } else {
            hso[b_loc * 17 + u_loc] = hn;
            __syncthreads();
            {
                int u2 = tid >> 4, b2 = tid & 15;
                float v = hso[b2 * 17 + u2];
                __stcg((float*)g_h[1 - par] + (u_base + u2) * B_ + b_base + b2, v);
            }
            __threadfence();
            __syncthreads();
            if (tid == 0) {
                atomicAdd(&g_bar, 1u);
                unsigned target = (unsigned)NCTA_REC * (unsigned)(t + 1);
                while (*barp < target) { }
            }
            __syncthreads();
        }
    }
}

// ---------------- launcher ----------------
extern "C" void kernel_launch(void* const* d_in, const int* in_sizes, int n_in,
                              void* d_out, int out_size) {
    const float* x  = (const float*)d_in[0];
    const float* W0 = (const float*)d_in[1];
    const float* R0 = (const float*)d_in[2];
    const float* b0 = (const float*)d_in[3];
    const float* W1 = (const float*)d_in[4];
    const float* R1 = (const float*)d_in[5];
    const float* b1 = (const float*)d_in[6];

    float* out  = (float*)d_out;
    float* out1 = out;                               // [64,1024,512]
    float* h0   = out + (size_t)B_ * T_ * U_;        // [64,512]
    float* h1   = h0 + (size_t)B_ * U_;              // [64,512]

    cudaFuncSetAttribute(gru_rec, cudaFuncAttributeMaxDynamicSharedMemorySize,
                         SMEM_REC_BYTES);
    cudaFuncSetAttribute(gemm_mma, cudaFuncAttributeMaxDynamicSharedMemorySize,
                         SMEM_GEMM_B);

    dim3 gg(12, 512);
    // layer 0
    split_w<<<NC_ * U_ / 256, 256>>>(W0);
    split_x<<<4096, 256>>>(x);
    gemm_mma<<<gg, 256, SMEM_GEMM_B>>>(b0);
    init_bar<<<1, 32>>>();
    gru_rec<<<NCTA_REC, 256, SMEM_REC_BYTES>>>(R0, b0, nullptr, 1, h0);
    // layer 1
    split_w<<<NC_ * U_ / 256, 256>>>(W1);
    gemm_mma<<<gg, 256, SMEM_GEMM_B>>>(b1);
    init_bar<<<1, 32>>>();
    gru_rec<<<NCTA_REC, 256, SMEM_REC_BYTES>>>(R1, b1, out1, 0, h1);
}

// round 6
// speedup vs baseline: 2.0394x; 1.0869x over previous
#include <cuda_runtime.h>
#include <cuda_fp16.h>
#include <cstdint>

#define B_  64
#define T_  1024
#define U_  512
#define NC_ 1536
#define M_  (B_ * T_)          // 65536
#define NCTA_REC 128
#define SMEM_REC_BYTES 158272
#define SMEM_GEMM 61952        // 2 stages * 30720 + 512 bias

// ---------------- device scratch ----------------
__device__ float    g_xp[(size_t)M_ * NC_];       // input projections
__device__ float    g_h [2][U_ * B_];             // h double buffer [par][u][b]
__device__ unsigned g_bar;
__device__ __half   g_a16[(size_t)M_ * U_];       // A (fp16) [m][k] — x, then y0
__device__ __half   g_wh0[(size_t)NC_ * U_];      // W0^T hi [n][k]
__device__ __half   g_wl0[(size_t)NC_ * U_];      // W0^T lo
__device__ __half   g_wh1[(size_t)NC_ * U_];      // W1^T hi
__device__ __half   g_wl1[(size_t)NC_ * U_];      // W1^T lo

// ---------------- f32x2 helpers (recurrence) ----------------
static __device__ __forceinline__ unsigned long long pack2(float x, float y) {
    unsigned long long r;
    asm("mov.b64 %0, {%1, %2};" : "=l"(r) : "f"(x), "f"(y));
    return r;
}
static __device__ __forceinline__ float2 unpack2(unsigned long long v) {
    float2 f;
    asm("mov.b64 {%0, %1}, %2;" : "=f"(f.x), "=f"(f.y) : "l"(v));
    return f;
}
static __device__ __forceinline__ void fma2(unsigned long long& d,
                                            unsigned long long a,
                                            unsigned long long b) {
    asm("fma.rn.f32x2 %0, %1, %2, %0;" : "+l"(d) : "l"(a), "l"(b));
}
static __device__ __forceinline__ float fsig(float x) {
    return __fdividef(1.0f, 1.0f + __expf(-x));
}
static __device__ __forceinline__ float ftanh(float x) {
    return 1.0f - __fdividef(2.0f, __expf(2.0f * x) + 1.0f);
}

// ---------------- mma / ldmatrix / cp.async helpers ----------------
static __device__ __forceinline__ uint32_t smem_u32(const void* p) {
    uint32_t a;
    asm("{ .reg .u64 t; cvta.to.shared.u64 t, %1; cvt.u32.u64 %0, t; }"
        : "=r"(a) : "l"(p));
    return a;
}
#define LDSM4(r, addr) \
    asm volatile("ldmatrix.sync.aligned.m8n8.x4.shared.b16 {%0,%1,%2,%3}, [%4];" \
        : "=r"((r)[0]), "=r"((r)[1]), "=r"((r)[2]), "=r"((r)[3]) : "r"(addr))
#define MMA_F16(d, a, b0v, b1v) \
    asm volatile("mma.sync.aligned.m16n8k16.row.col.f32.f16.f16.f32 " \
        "{%0,%1,%2,%3}, {%4,%5,%6,%7}, {%8,%9}, {%0,%1,%2,%3};" \
        : "+f"((d)[0]), "+f"((d)[1]), "+f"((d)[2]), "+f"((d)[3]) \
        : "r"((a)[0]), "r"((a)[1]), "r"((a)[2]), "r"((a)[3]), "r"(b0v), "r"(b1v))
#define CPA16(dst, src) \
    asm volatile("cp.async.cg.shared.global [%0], [%1], 16;" :: "r"(dst), "l"(src))
#define CPA_COMMIT() asm volatile("cp.async.commit_group;")
#define CPA_WAIT0()  asm volatile("cp.async.wait_group 0;" ::: "memory")

// ---------------- init barrier (once per launch) ----------------
__global__ void init_bar() { g_bar = 0u; }

// ---------------- split kernels ----------------
__global__ void split_x(const float* __restrict__ src) {
    size_t n = (size_t)M_ * U_;
    for (size_t i = (size_t)blockIdx.x * blockDim.x + threadIdx.x; i < n;
         i += (size_t)gridDim.x * blockDim.x)
        g_a16[i] = __float2half(src[i]);
}
__global__ void split_w(const float* __restrict__ W, int layer) {
    __half* wh = layer ? g_wh1 : g_wh0;
    __half* wl = layer ? g_wl1 : g_wl0;
    int idx = blockIdx.x * blockDim.x + threadIdx.x;   // out [n][k]
    if (idx < NC_ * U_) {
        int n = idx / U_, k = idx - n * U_;
        float v = W[(size_t)k * NC_ + n];
        __half h = __float2half(v);
        wh[idx] = h;
        wl[idx] = __float2half(v - __half2float(h));
    }
}

// ---------------- tensor-core GEMM (2-pass fp16): g_xp = A @ W^T + bias ----------------
// CTA 128m x 128n. 8 warps = 4m x 2n, warp tile 32x64. K in 16 tiles of 32.
// smem stage: A, Bh, Bl each 128x(32+8pad) halfs = 10240B; stage stride 30720.
__global__ __launch_bounds__(256) void gemm_mma(const float* __restrict__ bias, int layer) {
    extern __shared__ char sm[];
    const uint32_t sb = smem_u32(sm);
    float* bias_s = (float*)(sm + 61440);
    const __half* wh = layer ? g_wh1 : g_wh0;
    const __half* wl = layer ? g_wl1 : g_wl0;

    const int tid = threadIdx.x, lane = tid & 31, wid = tid >> 5;
    const int wm = wid >> 1, wn = wid & 1;
    const int m0 = blockIdx.y * 128, n0 = blockIdx.x * 128;

    if (tid < 128) bias_s[tid] = bias[n0 + tid];

    const int lrow = tid >> 2, lch = tid & 3;
    auto load_tile = [&](int kt, int stage) {
#pragma unroll
        for (int i = 0; i < 2; i++) {
            int row = lrow + i * 64;
            size_t go = (size_t)row * U_ + kt * 32 + lch * 8;
            uint32_t so = sb + stage * 30720 + row * 80 + lch * 16;
            CPA16(so,         (const char*)g_a16 + 2 * ((size_t)m0 * U_ + go));
            CPA16(so + 10240, (const char*)wh    + 2 * ((size_t)n0 * U_ + go));
            CPA16(so + 20480, (const char*)wl    + 2 * ((size_t)n0 * U_ + go));
        }
        CPA_COMMIT();
    };

    float acc[2][8][4];
#pragma unroll
    for (int f = 0; f < 2; f++)
#pragma unroll
        for (int j = 0; j < 8; j++)
#pragma unroll
            for (int c = 0; c < 4; c++) acc[f][j][c] = 0.f;

    const uint32_t aoff = (uint32_t)((wm * 32 + (lane & 15)) * 80 + ((lane >> 4) * 8) * 2);
    const uint32_t boff = (uint32_t)((wn * 64 + (lane & 7) + ((lane >> 4) & 1) * 8) * 80
                                     + (((lane >> 3) & 1) * 8) * 2);

    load_tile(0, 0);
    CPA_WAIT0();
    __syncthreads();

    int buf = 0;
#pragma unroll 1
    for (int kt = 0; kt < 16; kt++) {
        if (kt < 15) load_tile(kt + 1, buf ^ 1);
        const uint32_t sbase = sb + buf * 30720;
#pragma unroll
        for (int ks = 0; ks < 2; ks++) {
            const uint32_t kb = (uint32_t)(ks * 32);
            uint32_t a[2][4], bh[4][4], bl[4][4];
            LDSM4(a[0], sbase + aoff + kb);
            LDSM4(a[1], sbase + aoff + kb + 16 * 80);
#pragma unroll
            for (int p = 0; p < 4; p++) {
                LDSM4(bh[p], sbase + 10240 + boff + kb + p * 16 * 80);
                LDSM4(bl[p], sbase + 20480 + boff + kb + p * 16 * 80);
            }
#pragma unroll
            for (int f = 0; f < 2; f++)
#pragma unroll
                for (int j = 0; j < 8; j++) {
                    uint32_t h0 = bh[j >> 1][(j & 1) * 2], h1 = bh[j >> 1][(j & 1) * 2 + 1];
                    uint32_t l0 = bl[j >> 1][(j & 1) * 2], l1 = bl[j >> 1][(j & 1) * 2 + 1];
                    MMA_F16(acc[f][j], a[f], h0, h1);
                    MMA_F16(acc[f][j], a[f], l0, l1);
                }
        }
        if (kt < 15) {
            CPA_WAIT0();
            __syncthreads();
            buf ^= 1;
        }
    }

    // epilogue
#pragma unroll
    for (int f = 0; f < 2; f++) {
        const int r0 = m0 + wm * 32 + f * 16 + (lane >> 2);
#pragma unroll
        for (int j = 0; j < 8; j++) {
            const int cl = wn * 64 + j * 8 + (lane & 3) * 2;
            const int cg = n0 + cl;
            float2 o0 = make_float2(acc[f][j][0] + bias_s[cl], acc[f][j][1] + bias_s[cl + 1]);
            float2 o1 = make_float2(acc[f][j][2] + bias_s[cl], acc[f][j][3] + bias_s[cl + 1]);
            *(float2*)(g_xp + (size_t)r0 * NC_ + cg)       = o0;
            *(float2*)(g_xp + (size_t)(r0 + 8) * NC_ + cg) = o1;
        }
    }
}

// ---------------- persistent GRU recurrence ----------------
__global__ __launch_bounds__(256) void gru_rec(const float* __restrict__ R,
                                               const float* __restrict__ bvec,
                                               float* __restrict__ yext, int writeSplit,
                                               float* __restrict__ hlast,
                                               unsigned bar_base) {
    extern __shared__ float smf[];
    float* Rs  = smf;                       // [3][512][16]
    float* hs  = Rs + 3 * 512 * 16;         // [512][16]
    float* red = hs + 512 * 16;             // [8][3][16][17]
    float* hso = red + 8 * 3 * 16 * 17;     // [16][17]

    const int tid = threadIdx.x;
    const int bid = blockIdx.x;
    const int bg = bid >> 5, ug = bid & 31;
    const int b_base = bg * 16, u_base = ug * 16;

    for (int i = tid; i < 3 * 512 * 16; i += 256) {
        int g = i >> 13;
        int rem = i & 8191;
        int k = rem >> 4, j = rem & 15;
        Rs[i] = R[(size_t)k * NC_ + g * U_ + u_base + j];
    }

    const int b_loc = tid >> 4, u_loc = tid & 15;
    const int b_glob = b_base + b_loc, u_glob = u_base + u_loc;
    const float bz  = bvec[NC_ + u_glob];
    const float brr = bvec[NC_ + U_ + u_glob];
    const float bhh = bvec[NC_ + 2 * U_ + u_glob];
    const float* xpp = g_xp + (size_t)b_glob * T_ * NC_;
    const size_t orow = (size_t)b_glob * T_ * U_ + u_glob;

    const int w = tid >> 5, l = tid & 31;
    const int kbase = w * 64;
    const int bq = (l & 3) * 4;
    const int uq = (l >> 2) * 2;

    __syncthreads();

    // prefetch x projections for t=0
    float xz = __ldg(xpp + u_glob);
    float xr = __ldg(xpp + U_ + u_glob);
    float xh = __ldg(xpp + 2 * U_ + u_glob);

    for (int t = 0; t < T_; t++) {
        const int par = t & 1;
        if (t == 0) {
#pragma unroll
            for (int i = 0; i < 8; i++) {
                int idx = tid + i * 256;
                *(float4*)&hs[idx * 4] = make_float4(0.f, 0.f, 0.f, 0.f);
            }
        } else {
            const float* hg = g_h[par];
#pragma unroll
            for (int i = 0; i < 8; i++) {
                int idx = tid + i * 256;
                int u = idx >> 2, q = (idx & 3) * 4;
                float4 v = __ldcg((const float4*)(hg + u * B_ + b_base + q));
                *(float4*)&hs[u * 16 + q] = v;
            }
        }
        __syncthreads();

        unsigned long long acc[4][3];
#pragma unroll
        for (int i = 0; i < 4; i++)
#pragma unroll
            for (int g = 0; g < 3; g++) acc[i][g] = 0ull;

#pragma unroll 4
        for (int kk = 0; kk < 64; kk++) {
            int k = kbase + kk;
            float4 h4 = *(const float4*)&hs[k * 16 + bq];
            unsigned long long hh0 = pack2(h4.x, h4.x);
            unsigned long long hh1 = pack2(h4.y, h4.y);
            unsigned long long hh2 = pack2(h4.z, h4.z);
            unsigned long long hh3 = pack2(h4.w, h4.w);
#pragma unroll
            for (int g = 0; g < 3; g++) {
                unsigned long long rp = *(const unsigned long long*)&Rs[g * 8192 + k * 16 + uq];
                fma2(acc[0][g], hh0, rp);
                fma2(acc[1][g], hh1, rp);
                fma2(acc[2][g], hh2, rp);
                fma2(acc[3][g], hh3, rp);
            }
        }

#pragma unroll
        for (int g = 0; g < 3; g++) {
            int base = (w * 3 + g) * 16;
#pragma unroll
            for (int i = 0; i < 4; i++) {
                float2 f = unpack2(acc[i][g]);
                red[(base + bq + i) * 17 + uq]     = f.x;
                red[(base + bq + i) * 17 + uq + 1] = f.y;
            }
        }
        __syncthreads();

        float s0 = 0.f, s1 = 0.f, s2 = 0.f;
#pragma unroll
        for (int ww = 0; ww < 8; ww++) {
            s0 += red[((ww * 3 + 0) * 16 + b_loc) * 17 + u_loc];
            s1 += red[((ww * 3 + 1) * 16 + b_loc) * 17 + u_loc];
            s2 += red[((ww * 3 + 2) * 16 + b_loc) * 17 + u_loc];
        }
        float hold = hs[u_glob * 16 + b_loc];
        float z  = fsig(xz + s0 + bz);
        float r  = fsig(xr + s1 + brr);
        float hh = ftanh(xh + r * (s2 + bhh));
        float hn = z * hold + (1.0f - z) * hh;

        if (writeSplit) {
            g_a16[orow + (size_t)t * U_] = __float2half(hn);
        } else {
            yext[orow + (size_t)t * U_] = hn;
        }

        if (t == T_ - 1) {
            hlast[b_glob * U_ + u_glob] = hn;
        } else {
            hso[b_loc * 17 + u_loc] = hn;
            // prefetch next step's x while we sync/exchange
            float nxz = __ldg(xpp + (size_t)(t + 1) * NC_ + u_glob);
            float nxr = __ldg(xpp + (size_t)(t + 1) * NC_ + U_ + u_glob);
            float nxh = __ldg(xpp + (size_t)(t + 1) * NC_ + 2 * U_ + u_glob);
            __syncthreads();
            {
                int u2 = tid >> 4, b2 = tid & 15;
                float v = hso[b2 * 17 + u2];
                __stcg((float*)g_h[1 - par] + (u_base + u2) * B_ + b_base + b2, v);
            }
            __syncthreads();
            if (tid == 0) {
                asm volatile("red.release.gpu.global.add.u32 [%0], 1;"
                             :: "l"(&g_bar) : "memory");
                unsigned target = bar_base + (unsigned)NCTA_REC * (unsigned)(t + 1);
                unsigned cur;
                do {
                    asm volatile("ld.acquire.gpu.global.u32 %0, [%1];"
                                 : "=r"(cur) : "l"(&g_bar) : "memory");
                } while (cur < target);
            }
            __syncthreads();
            xz = nxz; xr = nxr; xh = nxh;
        }
    }
}

// ---------------- launcher ----------------
extern "C" void kernel_launch(void* const* d_in, const int* in_sizes, int n_in,
                              void* d_out, int out_size) {
    const float* x  = (const float*)d_in[0];
    const float* W0 = (const float*)d_in[1];
    const float* R0 = (const float*)d_in[2];
    const float* b0 = (const float*)d_in[3];
    const float* W1 = (const float*)d_in[4];
    const float* R1 = (const float*)d_in[5];
    const float* b1 = (const float*)d_in[6];

    float* out  = (float*)d_out;
    float* out1 = out;                               // [64,1024,512]
    float* h0   = out + (size_t)B_ * T_ * U_;        // [64,512]
    float* h1   = h0 + (size_t)B_ * U_;              // [64,512]

    cudaFuncSetAttribute(gru_rec, cudaFuncAttributeMaxDynamicSharedMemorySize,
                         SMEM_REC_BYTES);
    cudaFuncSetAttribute(gemm_mma, cudaFuncAttributeMaxDynamicSharedMemorySize,
                         SMEM_GEMM);

    dim3 gg(12, 512);
    init_bar<<<1, 32>>>();                                   // launch 0
    split_w<<<NC_ * U_ / 256, 256>>>(W0, 0);                 // launch 1
    split_w<<<NC_ * U_ / 256, 256>>>(W1, 1);                 // launch 2
    split_x<<<4096, 256>>>(x);                               // launch 3
    gemm_mma<<<gg, 256, SMEM_GEMM>>>(b0, 0);                 // launch 4
    gru_rec<<<NCTA_REC, 256, SMEM_REC_BYTES>>>(R0, b0, nullptr, 1, h0, 0u);       // launch 5 (ncu)
    gemm_mma<<<gg, 256, SMEM_GEMM>>>(b1, 1);
    gru_rec<<<NCTA_REC, 256, SMEM_REC_BYTES>>>(R1, b1, out1, 0, h1,
                                               (unsigned)NCTA_REC * (T_ - 1));
}

// round 9
// speedup vs baseline: 2.0983x; 1.0289x over previous
#include <cuda_runtime.h>
#include <cuda_fp16.h>
#include <cstdint>

#define B_  64
#define T_  1024
#define U_  512
#define NC_ 1536
#define M_  (B_ * T_)          // 65536
#define NREC 128
#define NCHASE 20
#define CHASE_TILES 1536       // t-chunks 0..1 of gemm1 (768 tiles per chunk)
#define SMEM_REC_BYTES 158272
#define SMEM_GEMM 61952        // 2 stages * 30720 + 512 bias

// ---------------- device scratch (454 MB total — same footprint as R6, which passed) ----
__device__ float    g_xp [(size_t)M_ * NC_];      // projections (layer 0, then layer 1 in-place)
__device__ float    g_h [2][U_ * B_];             // h double buffer [par][u][b]
__device__ unsigned g_bars[4 * 32];               // 4 group barriers, 128B apart
__device__ __half   g_a16[(size_t)M_ * U_];       // A (fp16) [m][k] — x, then y0
__device__ __half   g_wh0[(size_t)NC_ * U_];      // W0^T hi [n][k]
__device__ __half   g_wl0[(size_t)NC_ * U_];
__device__ __half   g_wh1[(size_t)NC_ * U_];      // W1^T hi
__device__ __half   g_wl1[(size_t)NC_ * U_];

// ---------------- f32x2 helpers ----------------
static __device__ __forceinline__ unsigned long long pack2(float x, float y) {
    unsigned long long r;
    asm("mov.b64 %0, {%1, %2};" : "=l"(r) : "f"(x), "f"(y));
    return r;
}
static __device__ __forceinline__ float2 unpack2(unsigned long long v) {
    float2 f;
    asm("mov.b64 {%0, %1}, %2;" : "=f"(f.x), "=f"(f.y) : "l"(v));
    return f;
}
static __device__ __forceinline__ void fma2(unsigned long long& d,
                                            unsigned long long a,
                                            unsigned long long b) {
    asm("fma.rn.f32x2 %0, %1, %2, %0;" : "+l"(d) : "l"(a), "l"(b));
}
static __device__ __forceinline__ float fsig(float x) {
    return __fdividef(1.0f, 1.0f + __expf(-x));
}
static __device__ __forceinline__ float ftanh(float x) {
    return 1.0f - __fdividef(2.0f, __expf(2.0f * x) + 1.0f);
}

// ---------------- mma / ldmatrix / cp.async helpers ----------------
static __device__ __forceinline__ uint32_t smem_u32(const void* p) {
    uint32_t a;
    asm("{ .reg .u64 t; cvta.to.shared.u64 t, %1; cvt.u32.u64 %0, t; }"
        : "=r"(a) : "l"(p));
    return a;
}
#define LDSM4(r, addr) \
    asm volatile("ldmatrix.sync.aligned.m8n8.x4.shared.b16 {%0,%1,%2,%3}, [%4];" \
        : "=r"((r)[0]), "=r"((r)[1]), "=r"((r)[2]), "=r"((r)[3]) : "r"(addr))
#define MMA_F16(d, a, b0v, b1v) \
    asm volatile("mma.sync.aligned.m16n8k16.row.col.f32.f16.f16.f32 " \
        "{%0,%1,%2,%3}, {%4,%5,%6,%7}, {%8,%9}, {%0,%1,%2,%3};" \
        : "+f"((d)[0]), "+f"((d)[1]), "+f"((d)[2]), "+f"((d)[3]) \
        : "r"((a)[0]), "r"((a)[1]), "r"((a)[2]), "r"((a)[3]), "r"(b0v), "r"(b1v))
#define CPA16(dst, src) \
    asm volatile("cp.async.cg.shared.global [%0], [%1], 16;" :: "r"(dst), "l"(src))
#define CPA_COMMIT() asm volatile("cp.async.commit_group;")
#define CPA_WAIT0()  asm volatile("cp.async.wait_group 0;" ::: "memory")

static __device__ __forceinline__ void bar_arrive(unsigned* p) {
    asm volatile("red.release.gpu.global.add.u32 [%0], 1;" :: "l"(p) : "memory");
}
static __device__ __forceinline__ void bar_poll(unsigned* p, unsigned target) {
    unsigned cur;
    do {
        asm volatile("ld.acquire.gpu.global.u32 %0, [%1];"
                     : "=r"(cur) : "l"(p) : "memory");
    } while (cur < target);
}

// ---------------- split kernels ----------------
__global__ void split_x(const float* __restrict__ src) {
    size_t n = (size_t)M_ * U_;
    for (size_t i = (size_t)blockIdx.x * blockDim.x + threadIdx.x; i < n;
         i += (size_t)gridDim.x * blockDim.x)
        g_a16[i] = __float2half(src[i]);
}
__global__ void split_w(const float* __restrict__ W, int layer) {
    if (layer == 0 && blockIdx.x == 0 && threadIdx.x < 4)
        g_bars[threadIdx.x * 32] = 0u;
    __half* wh = layer ? g_wh1 : g_wh0;
    __half* wl = layer ? g_wl1 : g_wl0;
    int idx = blockIdx.x * blockDim.x + threadIdx.x;   // out [n][k]
    if (idx < NC_ * U_) {
        int n = idx / U_, k = idx - n * U_;
        float v = W[(size_t)k * NC_ + n];
        __half h = __float2half(v);
        wh[idx] = h;
        wl[idx] = __float2half(v - __half2float(h));
    }
}

// ---------------- one 128x128 GEMM tile (2-pass fp16), force-inlined ----------------
// smem: [0,61440) two 30720B stages (A,Bh,Bl each 128x(32+8pad) halfs); [61440,+512) bias.
static __device__ __forceinline__ void gemm_tile(const __half* __restrict__ wh,
                                                 const __half* __restrict__ wl,
                                                 const float* __restrict__ biasv,
                                                 float* __restrict__ Cout,
                                                 int m0, int n0, char* sm, uint32_t sb) {
    float* bias_s = (float*)(sm + 61440);
    const int tid = threadIdx.x, lane = tid & 31, wid = tid >> 5;
    const int wm = wid >> 1, wn = wid & 1;

    __syncthreads();                      // previous tile fully consumed
    if (tid < 128) bias_s[tid] = biasv[n0 + tid];

    const int lrow = tid >> 2, lch = tid & 3;
    auto load_tile = [&](int kt, int stage) {
#pragma unroll
        for (int i = 0; i < 2; i++) {
            int row = lrow + i * 64;
            size_t go = (size_t)row * U_ + kt * 32 + lch * 8;
            uint32_t so = sb + stage * 30720 + row * 80 + lch * 16;
            CPA16(so,         (const char*)g_a16 + 2 * ((size_t)m0 * U_ + go));
            CPA16(so + 10240, (const char*)wh    + 2 * ((size_t)n0 * U_ + go));
            CPA16(so + 20480, (const char*)wl    + 2 * ((size_t)n0 * U_ + go));
        }
        CPA_COMMIT();
    };

    float acc[2][8][4];
#pragma unroll
    for (int f = 0; f < 2; f++)
#pragma unroll
        for (int j = 0; j < 8; j++)
#pragma unroll
            for (int c = 0; c < 4; c++) acc[f][j][c] = 0.f;

    const uint32_t aoff = (uint32_t)((wm * 32 + (lane & 15)) * 80 + ((lane >> 4) * 8) * 2);
    const uint32_t boff = (uint32_t)((wn * 64 + (lane & 7) + ((lane >> 4) & 1) * 8) * 80
                                     + (((lane >> 3) & 1) * 8) * 2);

    load_tile(0, 0);
    CPA_WAIT0();
    __syncthreads();

    int buf = 0;
#pragma unroll 1
    for (int kt = 0; kt < 16; kt++) {
        if (kt < 15) load_tile(kt + 1, buf ^ 1);
        const uint32_t sbase = sb + buf * 30720;
#pragma unroll
        for (int ks = 0; ks < 2; ks++) {
            const uint32_t kb = (uint32_t)(ks * 32);
            uint32_t a[2][4], bh[4][4], bl[4][4];
            LDSM4(a[0], sbase + aoff + kb);
            LDSM4(a[1], sbase + aoff + kb + 16 * 80);
#pragma unroll
            for (int p = 0; p < 4; p++) {
                LDSM4(bh[p], sbase + 10240 + boff + kb + p * 16 * 80);
                LDSM4(bl[p], sbase + 20480 + boff + kb + p * 16 * 80);
            }
#pragma unroll
            for (int f = 0; f < 2; f++)
#pragma unroll
                for (int j = 0; j < 8; j++) {
                    uint32_t h0 = bh[j >> 1][(j & 1) * 2], h1 = bh[j >> 1][(j & 1) * 2 + 1];
                    uint32_t l0 = bl[j >> 1][(j & 1) * 2], l1 = bl[j >> 1][(j & 1) * 2 + 1];
                    MMA_F16(acc[f][j], a[f], h0, h1);
                    MMA_F16(acc[f][j], a[f], l0, l1);
                }
        }
        if (kt < 15) {
            CPA_WAIT0();
            __syncthreads();
            buf ^= 1;
        }
    }

#pragma unroll
    for (int f = 0; f < 2; f++) {
        const int r0 = m0 + wm * 32 + f * 16 + (lane >> 2);
#pragma unroll
        for (int j = 0; j < 8; j++) {
            const int cl = wn * 64 + j * 8 + (lane & 3) * 2;
            const int cg = n0 + cl;
            float2 o0 = make_float2(acc[f][j][0] + bias_s[cl], acc[f][j][1] + bias_s[cl + 1]);
            float2 o1 = make_float2(acc[f][j][2] + bias_s[cl], acc[f][j][3] + bias_s[cl + 1]);
            *(float2*)(Cout + (size_t)r0 * NC_ + cg)       = o0;
            *(float2*)(Cout + (size_t)(r0 + 8) * NC_ + cg) = o1;
        }
    }
}

// ---------------- GEMM kernels ----------------
// mode 0: layer-0 full (my = blockIdx.y, 512 m-tiles) -> g_xp.
// mode 1: layer-1 rest (t-chunks 2..7) -> g_xp in place (rec0 already done).
__global__ __launch_bounds__(256) void gemm_mma(const float* __restrict__ bias, int mode) {
    extern __shared__ char sm[];
    const uint32_t sb = smem_u32(sm);
    int my, n0 = blockIdx.x * 128;
    const __half *wh, *wl;
    if (mode == 0) { my = blockIdx.y; wh = g_wh0; wl = g_wl0; }
    else {
        int yy = blockIdx.y;
        my = (yy / 6) * 8 + 2 + (yy % 6);
        wh = g_wh1; wl = g_wl1;
    }
    gemm_tile(wh, wl, bias, g_xp, my * 128, n0, sm, sb);
}

// ---------------- persistent GRU recurrence + gemm1 chasers ----------------
__global__ __launch_bounds__(256) void gru_rec(const float* __restrict__ R,
                                               const float* __restrict__ bvec,
                                               float* __restrict__ yext, int writeSplit,
                                               float* __restrict__ hlast,
                                               unsigned bar_base,
                                               const float* __restrict__ bias1) {
    extern __shared__ float smf[];
    const int tid = threadIdx.x;
    const int bid = blockIdx.x;

    if (bid >= NREC) {
        // ---- chaser: layer-1 projection tiles for t-chunks 0..1, in-place into g_xp.
        // Safe: tile rows tc*128..tc*128+127 are dead once the b-group's counter
        // reaches 32*(tc+1)*128 (every CTA finished step (tc+1)*128-1 and already
        // prefetched row (tc+1)*128).
        char* sm = (char*)smf;
        const uint32_t sb = smem_u32(sm);
        const int cid = bid - NREC;
        for (int tt = cid; tt < CHASE_TILES; tt += NCHASE) {
            int tc = tt / 768, rem = tt % 768;
            int b = rem / 12, nn = rem % 12;
            unsigned need = 32u * (unsigned)(tc * 128 + 128);
            if (tid == 0) bar_poll(&g_bars[(b >> 4) * 32], need);
            __syncthreads();
            gemm_tile(g_wh1, g_wl1, bias1, g_xp, (b * 8 + tc) * 128, nn * 128, sm, sb);
        }
        return;
    }

    float* Rs  = smf;                       // [3][512][16]
    float* hs  = Rs + 3 * 512 * 16;         // [512][16]
    float* red = hs + 512 * 16;             // [8][3][16][17]
    float* hso = red + 8 * 3 * 16 * 17;     // [16][17]

    const int bg = bid >> 5, ug = bid & 31;
    const int b_base = bg * 16, u_base = ug * 16;
    unsigned* mybar = &g_bars[bg * 32];

    for (int i = tid; i < 3 * 512 * 16; i += 256) {
        int g = i >> 13;
        int rem = i & 8191;
        int k = rem >> 4, j = rem & 15;
        Rs[i] = R[(size_t)k * NC_ + g * U_ + u_base + j];
    }

    const int b_loc = tid >> 4, u_loc = tid & 15;
    const int b_glob = b_base + b_loc, u_glob = u_base + u_loc;
    const float bz  = bvec[NC_ + u_glob];
    const float brr = bvec[NC_ + U_ + u_glob];
    const float bhh = bvec[NC_ + 2 * U_ + u_glob];
    const float* xpp = g_xp + (size_t)b_glob * T_ * NC_;
    const size_t orow = (size_t)b_glob * T_ * U_ + u_glob;

    const int w = tid >> 5, l = tid & 31;
    const int kbase = w * 64;
    const int bq = (l & 3) * 4;
    const int uq = (l >> 2) * 2;

    __syncthreads();

    float xz = __ldg(xpp + u_glob);
    float xr = __ldg(xpp + U_ + u_glob);
    float xh = __ldg(xpp + 2 * U_ + u_glob);

    for (int t = 0; t < T_; t++) {
        const int par = t & 1;
        if (t == 0) {
#pragma unroll
            for (int i = 0; i < 8; i++) {
                int idx = tid + i * 256;
                *(float4*)&hs[idx * 4] = make_float4(0.f, 0.f, 0.f, 0.f);
            }
        } else {
            const float* hg = g_h[par];
#pragma unroll
            for (int i = 0; i < 8; i++) {
                int idx = tid + i * 256;
                int u = idx >> 2, q = (idx & 3) * 4;
                float4 v = __ldcg((const float4*)(hg + u * B_ + b_base + q));
                *(float4*)&hs[u * 16 + q] = v;
            }
        }
        __syncthreads();

        unsigned long long acc[4][3];
#pragma unroll
        for (int i = 0; i < 4; i++)
#pragma unroll
            for (int g = 0; g < 3; g++) acc[i][g] = 0ull;

#pragma unroll 4
        for (int kk = 0; kk < 64; kk++) {
            int k = kbase + kk;
            float4 h4 = *(const float4*)&hs[k * 16 + bq];
            unsigned long long hh0 = pack2(h4.x, h4.x);
            unsigned long long hh1 = pack2(h4.y, h4.y);
            unsigned long long hh2 = pack2(h4.z, h4.z);
            unsigned long long hh3 = pack2(h4.w, h4.w);
#pragma unroll
            for (int g = 0; g < 3; g++) {
                unsigned long long rp = *(const unsigned long long*)&Rs[g * 8192 + k * 16 + uq];
                fma2(acc[0][g], hh0, rp);
                fma2(acc[1][g], hh1, rp);
                fma2(acc[2][g], hh2, rp);
                fma2(acc[3][g], hh3, rp);
            }
        }

#pragma unroll
        for (int g = 0; g < 3; g++) {
            int base = (w * 3 + g) * 16;
#pragma unroll
            for (int i = 0; i < 4; i++) {
                float2 f = unpack2(acc[i][g]);
                red[(base + bq + i) * 17 + uq]     = f.x;
                red[(base + bq + i) * 17 + uq + 1] = f.y;
            }
        }
        __syncthreads();

        float s0 = 0.f, s1 = 0.f, s2 = 0.f;
#pragma unroll
        for (int ww = 0; ww < 8; ww++) {
            s0 += red[((ww * 3 + 0) * 16 + b_loc) * 17 + u_loc];
            s1 += red[((ww * 3 + 1) * 16 + b_loc) * 17 + u_loc];
            s2 += red[((ww * 3 + 2) * 16 + b_loc) * 17 + u_loc];
        }
        float hold = hs[u_glob * 16 + b_loc];
        float z  = fsig(xz + s0 + bz);
        float r  = fsig(xr + s1 + brr);
        float hh = ftanh(xh + r * (s2 + bhh));
        float hn = z * hold + (1.0f - z) * hh;

        if (writeSplit) {
            g_a16[orow + (size_t)t * U_] = __float2half(hn);
        } else {
            yext[orow + (size_t)t * U_] = hn;
        }

        if (t == T_ - 1) {
            hlast[b_glob * U_ + u_glob] = hn;
        } else {
            hso[b_loc * 17 + u_loc] = hn;
            float nxz = __ldg(xpp + (size_t)(t + 1) * NC_ + u_glob);
            float nxr = __ldg(xpp + (size_t)(t + 1) * NC_ + U_ + u_glob);
            float nxh = __ldg(xpp + (size_t)(t + 1) * NC_ + 2 * U_ + u_glob);
            __syncthreads();
            {
                int u2 = tid >> 4, b2 = tid & 15;
                float v = hso[b2 * 17 + u2];
                __stcg((float*)g_h[1 - par] + (u_base + u2) * B_ + b_base + b2, v);
            }
            __syncthreads();
            if (tid == 0) {
                bar_arrive(mybar);
                bar_poll(mybar, bar_base + 32u * (unsigned)(t + 1));
            }
            __syncthreads();
            xz = nxz; xr = nxr; xh = nxh;
        }
    }
}

// ---------------- launcher ----------------
extern "C" void kernel_launch(void* const* d_in, const int* in_sizes, int n_in,
                              void* d_out, int out_size) {
    const float* x  = (const float*)d_in[0];
    const float* W0 = (const float*)d_in[1];
    const float* R0 = (const float*)d_in[2];
    const float* b0 = (const float*)d_in[3];
    const float* W1 = (const float*)d_in[4];
    const float* R1 = (const float*)d_in[5];
    const float* b1 = (const float*)d_in[6];

    float* out  = (float*)d_out;
    float* out1 = out;                               // [64,1024,512]
    float* h0   = out + (size_t)B_ * T_ * U_;        // [64,512]
    float* h1   = h0 + (size_t)B_ * U_;              // [64,512]

    cudaFuncSetAttribute(gru_rec, cudaFuncAttributeMaxDynamicSharedMemorySize,
                         SMEM_REC_BYTES);
    cudaFuncSetAttribute(gemm_mma, cudaFuncAttributeMaxDynamicSharedMemorySize,
                         SMEM_GEMM);

    split_w<<<NC_ * U_ / 256, 256>>>(W0, 0);                 // my launch 0
    split_w<<<NC_ * U_ / 256, 256>>>(W1, 1);                 // 1
    split_x<<<4096, 256>>>(x);                               // 2
    dim3 g0(12, 512);
    gemm_mma<<<g0, 256, SMEM_GEMM>>>(b0, 0);                 // 3 -> ncu (-s 5 incl. 2 harness)
    gru_rec<<<NREC + NCHASE, 256, SMEM_REC_BYTES>>>(R0, b0, nullptr, 1, h0, 0u, b1);
    dim3 g1(12, 384);
    gemm_mma<<<g1, 256, SMEM_GEMM>>>(b1, 1);                 // t-chunks 2..7
    gru_rec<<<NREC, 256, SMEM_REC_BYTES>>>(R1, b1, out1, 0, h1,
                                           32u * (T_ - 1), nullptr);
}

// round 10
// speedup vs baseline: 3.4031x; 1.6218x over previous
#include <cuda_runtime.h>
#include <cuda_fp16.h>
#include <cstdint>

#define B_  64
#define T_  1024
#define U_  512
#define NC_ 1536
#define M_  (B_ * T_)          // 65536
#define NREC 128
#define NCHASE 20
#define CHASE_TILES 1536       // t-chunks 0..1 of gemm1 (768 tiles per chunk)
#define SMEM_REC_BYTES 122880  // > 114KB: forces 1 CTA/SM for the persistent grid
#define SMEM_GEMM 61952        // 2 stages * 30720 + 512 bias

// ---------------- device scratch (~457 MB, ~R6 footprint which passed) ----------------
__device__ float    g_xp [(size_t)M_ * NC_];      // projections (layer 0, then layer 1 in-place)
__device__ unsigned g_hx [2][B_ * U_];            // h exchange: packed fp16 hi|lo, [par][b][u]
__device__ unsigned g_bars[4 * 32];               // 4 group barriers, 128B apart
__device__ __half   g_a16[(size_t)M_ * U_];       // A (fp16) [m][k] — x, then y0
__device__ __half   g_wh0[(size_t)NC_ * U_];      // W0^T hi [n][k]
__device__ __half   g_wl0[(size_t)NC_ * U_];
__device__ __half   g_wh1[(size_t)NC_ * U_];      // W1^T hi
__device__ __half   g_wl1[(size_t)NC_ * U_];
__device__ __half   g_r0 [(size_t)NC_ * U_];      // R0^T fp16 [n=g*512+u][k]
__device__ __half   g_r1 [(size_t)NC_ * U_];      // R1^T fp16

// ---------------- helpers ----------------
static __device__ __forceinline__ float fsig(float x) {
    return __fdividef(1.0f, 1.0f + __expf(-x));
}
static __device__ __forceinline__ float ftanh(float x) {
    return 1.0f - __fdividef(2.0f, __expf(2.0f * x) + 1.0f);
}
static __device__ __forceinline__ uint32_t smem_u32(const void* p) {
    uint32_t a;
    asm("{ .reg .u64 t; cvta.to.shared.u64 t, %1; cvt.u32.u64 %0, t; }"
        : "=r"(a) : "l"(p));
    return a;
}
#define LDSM4(r, addr) \
    asm volatile("ldmatrix.sync.aligned.m8n8.x4.shared.b16 {%0,%1,%2,%3}, [%4];" \
        : "=r"((r)[0]), "=r"((r)[1]), "=r"((r)[2]), "=r"((r)[3]) : "r"(addr))
#define MMA_F16(d, a, b0v, b1v) \
    asm volatile("mma.sync.aligned.m16n8k16.row.col.f32.f16.f16.f32 " \
        "{%0,%1,%2,%3}, {%4,%5,%6,%7}, {%8,%9}, {%0,%1,%2,%3};" \
        : "+f"((d)[0]), "+f"((d)[1]), "+f"((d)[2]), "+f"((d)[3]) \
        : "r"((a)[0]), "r"((a)[1]), "r"((a)[2]), "r"((a)[3]), "r"(b0v), "r"(b1v))
#define CPA16(dst, src) \
    asm volatile("cp.async.cg.shared.global [%0], [%1], 16;" :: "r"(dst), "l"(src))
#define CPA_COMMIT() asm volatile("cp.async.commit_group;")
#define CPA_WAIT0()  asm volatile("cp.async.wait_group 0;" ::: "memory")

static __device__ __forceinline__ void bar_arrive(unsigned* p) {
    asm volatile("red.release.gpu.global.add.u32 [%0], 1;" :: "l"(p) : "memory");
}
static __device__ __forceinline__ void bar_poll(unsigned* p, unsigned target) {
    unsigned cur;
    do {
        asm volatile("ld.acquire.gpu.global.u32 %0, [%1];"
                     : "=r"(cur) : "l"(p) : "memory");
    } while (cur < target);
}

// ---------------- prep: all weight conversions in ONE kernel ----------------
// i -> (n, k): n = i>>9 (0..1535), k = i&511.
__global__ void prep_weights(const float* __restrict__ W0, const float* __restrict__ W1,
                             const float* __restrict__ R0, const float* __restrict__ R1) {
    if (blockIdx.x == 0 && threadIdx.x < 4) g_bars[threadIdx.x * 32] = 0u;
    int i = blockIdx.x * blockDim.x + threadIdx.x;
    if (i < NC_ * U_) {
        int n = i >> 9, k = i & 511;
        float v0 = W0[(size_t)k * NC_ + n];
        __half h0 = __float2half(v0);
        g_wh0[i] = h0;
        g_wl0[i] = __float2half(v0 - __half2float(h0));
        float v1 = W1[(size_t)k * NC_ + n];
        __half h1 = __float2half(v1);
        g_wh1[i] = h1;
        g_wl1[i] = __float2half(v1 - __half2float(h1));
        g_r0[i] = __float2half(R0[(size_t)k * NC_ + n]);
        g_r1[i] = __float2half(R1[(size_t)k * NC_ + n]);
    }
}

__global__ void split_x(const float* __restrict__ src) {
    size_t n = (size_t)M_ * U_;
    for (size_t i = (size_t)blockIdx.x * blockDim.x + threadIdx.x; i < n;
         i += (size_t)gridDim.x * blockDim.x)
        g_a16[i] = __float2half(src[i]);
}

// ---------------- one 128x128 GEMM tile (2-pass fp16), force-inlined ----------------
static __device__ __forceinline__ void gemm_tile(const __half* __restrict__ wh,
                                                 const __half* __restrict__ wl,
                                                 const float* __restrict__ biasv,
                                                 float* __restrict__ Cout,
                                                 int m0, int n0, char* sm, uint32_t sb) {
    float* bias_s = (float*)(sm + 61440);
    const int tid = threadIdx.x, lane = tid & 31, wid = tid >> 5;
    const int wm = wid >> 1, wn = wid & 1;

    __syncthreads();
    if (tid < 128) bias_s[tid] = biasv[n0 + tid];

    const int lrow = tid >> 2, lch = tid & 3;
    auto load_tile = [&](int kt, int stage) {
#pragma unroll
        for (int i = 0; i < 2; i++) {
            int row = lrow + i * 64;
            size_t go = (size_t)row * U_ + kt * 32 + lch * 8;
            uint32_t so = sb + stage * 30720 + row * 80 + lch * 16;
            CPA16(so,         (const char*)g_a16 + 2 * ((size_t)m0 * U_ + go));
            CPA16(so + 10240, (const char*)wh    + 2 * ((size_t)n0 * U_ + go));
            CPA16(so + 20480, (const char*)wl    + 2 * ((size_t)n0 * U_ + go));
        }
        CPA_COMMIT();
    };

    float acc[2][8][4];
#pragma unroll
    for (int f = 0; f < 2; f++)
#pragma unroll
        for (int j = 0; j < 8; j++)
#pragma unroll
            for (int c = 0; c < 4; c++) acc[f][j][c] = 0.f;

    const uint32_t aoff = (uint32_t)((wm * 32 + (lane & 15)) * 80 + ((lane >> 4) * 8) * 2);
    const uint32_t boff = (uint32_t)((wn * 64 + (lane & 7) + ((lane >> 4) & 1) * 8) * 80
                                     + (((lane >> 3) & 1) * 8) * 2);

    load_tile(0, 0);
    CPA_WAIT0();
    __syncthreads();

    int buf = 0;
#pragma unroll 1
    for (int kt = 0; kt < 16; kt++) {
        if (kt < 15) load_tile(kt + 1, buf ^ 1);
        const uint32_t sbase = sb + buf * 30720;
#pragma unroll
        for (int ks = 0; ks < 2; ks++) {
            const uint32_t kb = (uint32_t)(ks * 32);
            uint32_t a[2][4], bh[4][4], bl[4][4];
            LDSM4(a[0], sbase + aoff + kb);
            LDSM4(a[1], sbase + aoff + kb + 16 * 80);
#pragma unroll
            for (int p = 0; p < 4; p++) {
                LDSM4(bh[p], sbase + 10240 + boff + kb + p * 16 * 80);
                LDSM4(bl[p], sbase + 20480 + boff + kb + p * 16 * 80);
            }
#pragma unroll
            for (int f = 0; f < 2; f++)
#pragma unroll
                for (int j = 0; j < 8; j++) {
                    uint32_t h0 = bh[j >> 1][(j & 1) * 2], h1 = bh[j >> 1][(j & 1) * 2 + 1];
                    uint32_t l0 = bl[j >> 1][(j & 1) * 2], l1 = bl[j >> 1][(j & 1) * 2 + 1];
                    MMA_F16(acc[f][j], a[f], h0, h1);
                    MMA_F16(acc[f][j], a[f], l0, l1);
                }
        }
        if (kt < 15) {
            CPA_WAIT0();
            __syncthreads();
            buf ^= 1;
        }
    }

#pragma unroll
    for (int f = 0; f < 2; f++) {
        const int r0 = m0 + wm * 32 + f * 16 + (lane >> 2);
#pragma unroll
        for (int j = 0; j < 8; j++) {
            const int cl = wn * 64 + j * 8 + (lane & 3) * 2;
            const int cg = n0 + cl;
            float2 o0 = make_float2(acc[f][j][0] + bias_s[cl], acc[f][j][1] + bias_s[cl + 1]);
            float2 o1 = make_float2(acc[f][j][2] + bias_s[cl], acc[f][j][3] + bias_s[cl + 1]);
            *(float2*)(Cout + (size_t)r0 * NC_ + cg)       = o0;
            *(float2*)(Cout + (size_t)(r0 + 8) * NC_ + cg) = o1;
        }
    }
}

// mode 0: layer-0 full. mode 1: layer-1 t-chunks 2..7 in-place.
__global__ __launch_bounds__(256) void gemm_mma(const float* __restrict__ bias, int mode) {
    extern __shared__ char smg[];
    const uint32_t sb = smem_u32(smg);
    int my, n0 = blockIdx.x * 128;
    const __half *wh, *wl;
    if (mode == 0) { my = blockIdx.y; wh = g_wh0; wl = g_wl0; }
    else {
        int yy = blockIdx.y;
        my = (yy / 6) * 8 + 2 + (yy % 6);
        wh = g_wh1; wl = g_wl1;
    }
    gemm_tile(wh, wl, bias, g_xp, my * 128, n0, smg, sb);
}

// ---------------- persistent GRU recurrence (mma.sync mainloop) + chasers ----------------
// rec CTA: 16 b x 16 u x 3 gates = C[16,48]; 8 warps k-split 64 each; 2-pass h hi/lo fp16.
// smem: h16hi [16][520] halfs @0 (stride 1040B); h16lo @16640; red [8][16][50] f32 @33280.
__global__ __launch_bounds__(256, 1) void gru_rec(int layer,
                                                  const float* __restrict__ bvec,
                                                  float* __restrict__ yext, int writeSplit,
                                                  float* __restrict__ hlast,
                                                  unsigned bar_base,
                                                  const float* __restrict__ bias1) {
    extern __shared__ char smb[];
    const int tid = threadIdx.x;
    const int bid = blockIdx.x;

    if (bid >= NREC) {
        // chaser: layer-1 projection tiles, t-chunks 0..1, in-place into g_xp (rows dead).
        const uint32_t sb = smem_u32(smb);
        const int cid = bid - NREC;
        for (int tt = cid; tt < CHASE_TILES; tt += NCHASE) {
            int tc = tt / 768, rem = tt % 768;
            int b = rem / 12, nn = rem % 12;
            unsigned need = 32u * (unsigned)(tc * 128 + 128);
            if (tid == 0) bar_poll(&g_bars[(b >> 4) * 32], need);
            __syncthreads();
            gemm_tile(g_wh1, g_wl1, bias1, g_xp, (b * 8 + tc) * 128, nn * 128, smb, sb);
        }
        return;
    }

    __half* h16hi = (__half*)smb;
    __half* h16lo = (__half*)(smb + 16640);
    float*  red   = (float*)(smb + 33280);
    const __half* R16 = layer ? g_r1 : g_r0;

    const int bg = bid >> 5, ug = bid & 31;
    const int b_base = bg * 16, u_base = ug * 16;
    unsigned* mybar = &g_bars[bg * 32];

    const int lane = tid & 31, w = tid >> 5;
    const int kbase = w * 64;

    // ---- preload R fragments into registers: [6 n-tiles][4 k-steps][2 regs] ----
    uint32_t rb[6][4][2];
    {
        const int nl = lane >> 2, kq = (lane & 3) * 2;
#pragma unroll
        for (int nt = 0; nt < 6; nt++) {
            int ncol = nt * 8 + nl;                   // 0..47
            int g = ncol >> 4, ul = ncol & 15;
            const __half* rp = R16 + ((size_t)(g * 512 + u_base + ul)) * 512;
#pragma unroll
            for (int ks = 0; ks < 4; ks++) {
                int k0 = kbase + ks * 16 + kq;
                rb[nt][ks][0] = *(const uint32_t*)(rp + k0);
                rb[nt][ks][1] = *(const uint32_t*)(rp + k0 + 8);
            }
        }
    }

    const int b_loc = tid >> 4, u_loc = tid & 15;
    const int b_glob = b_base + b_loc, u_glob = u_base + u_loc;
    const float bz  = bvec[NC_ + u_glob];
    const float brr = bvec[NC_ + U_ + u_glob];
    const float bhh = bvec[NC_ + 2 * U_ + u_glob];
    const float* xpp = g_xp + (size_t)b_glob * T_ * NC_;
    const size_t orow = (size_t)b_glob * T_ * U_ + u_glob;

    const uint32_t sb0 = smem_u32(smb);
    const uint32_t aoff = sb0 + (uint32_t)((lane & 15) * 1040 + (lane >> 4) * 16 + kbase * 2);

    float xz = __ldg(xpp + u_glob);
    float xr = __ldg(xpp + U_ + u_glob);
    float xh = __ldg(xpp + 2 * U_ + u_glob);

    for (int t = 0; t < T_; t++) {
        const int par = t & 1;
        if (t == 0) {
            for (int i = tid; i < 2080; i += 256)
                ((uint4*)smb)[i] = make_uint4(0u, 0u, 0u, 0u);
        } else {
            const unsigned* hg = g_hx[par];
#pragma unroll
            for (int i = 0; i < 8; i++) {
                int c = tid + i * 256;                // 0..2047
                int b = c >> 7, u0 = (c & 127) * 4;
                uint4 v = __ldcg((const uint4*)(hg + (size_t)(b_base + b) * U_ + u0));
                uint32_t hi01 = __byte_perm(v.x, v.y, 0x5410);
                uint32_t lo01 = __byte_perm(v.x, v.y, 0x7632);
                uint32_t hi23 = __byte_perm(v.z, v.w, 0x5410);
                uint32_t lo23 = __byte_perm(v.z, v.w, 0x7632);
                *(uint2*)(smb + b * 1040 + u0 * 2)         = make_uint2(hi01, hi23);
                *(uint2*)(smb + 16640 + b * 1040 + u0 * 2) = make_uint2(lo01, lo23);
            }
        }
        __syncthreads();

        // ---- mma mainloop ----
        float acc[6][4];
#pragma unroll
        for (int nt = 0; nt < 6; nt++)
#pragma unroll
            for (int c = 0; c < 4; c++) acc[nt][c] = 0.f;

        uint32_t ahi[4][4], alo[4][4];
#pragma unroll
        for (int ks = 0; ks < 4; ks++) {
            LDSM4(ahi[ks], aoff + ks * 32);
            LDSM4(alo[ks], aoff + 16640 + ks * 32);
        }
#pragma unroll
        for (int ks = 0; ks < 4; ks++) {
#pragma unroll
            for (int nt = 0; nt < 6; nt++)
                MMA_F16(acc[nt], ahi[ks], rb[nt][ks][0], rb[nt][ks][1]);
#pragma unroll
            for (int nt = 0; nt < 6; nt++)
                MMA_F16(acc[nt], alo[ks], rb[nt][ks][0], rb[nt][ks][1]);
        }

        // ---- store C fragments to red[w][b][n] ----
        {
            const int m = lane >> 2, n0 = (lane & 3) * 2;
            float* rw = red + (size_t)(w * 16) * 50;
#pragma unroll
            for (int nt = 0; nt < 6; nt++) {
                *(float2*)(rw + m * 50 + nt * 8 + n0)       = make_float2(acc[nt][0], acc[nt][1]);
                *(float2*)(rw + (m + 8) * 50 + nt * 8 + n0) = make_float2(acc[nt][2], acc[nt][3]);
            }
        }
        __syncthreads();

        // ---- owner: reduce 8 warps, gates ----
        float s0 = 0.f, s1 = 0.f, s2 = 0.f;
#pragma unroll
        for (int ww = 0; ww < 8; ww++) {
            const float* rr = red + (size_t)(ww * 16 + b_loc) * 50;
            s0 += rr[u_loc];
            s1 += rr[16 + u_loc];
            s2 += rr[32 + u_loc];
        }
        float hold = __half2float(h16hi[b_loc * 520 + u_glob]) +
                     __half2float(h16lo[b_loc * 520 + u_glob]);
        float z  = fsig(xz + s0 + bz);
        float r  = fsig(xr + s1 + brr);
        float hh = ftanh(xh + r * (s2 + bhh));
        float hn = z * hold + (1.0f - z) * hh;

        if (writeSplit) {
            g_a16[orow + (size_t)t * U_] = __float2half(hn);
        } else {
            yext[orow + (size_t)t * U_] = hn;
        }

        if (t == T_ - 1) {
            hlast[b_glob * U_ + u_glob] = hn;
        } else {
            __half hi = __float2half(hn);
            __half lo = __float2half(hn - __half2float(hi));
            unsigned hv = (unsigned)__half_as_ushort(hi) |
                          ((unsigned)__half_as_ushort(lo) << 16);
            __stcg(&g_hx[1 - par][(size_t)b_glob * U_ + u_glob], hv);
            float nxz = __ldg(xpp + (size_t)(t + 1) * NC_ + u_glob);
            float nxr = __ldg(xpp + (size_t)(t + 1) * NC_ + U_ + u_glob);
            float nxh = __ldg(xpp + (size_t)(t + 1) * NC_ + 2 * U_ + u_glob);
            __syncthreads();
            if (tid == 0) {
                bar_arrive(mybar);
                bar_poll(mybar, bar_base + 32u * (unsigned)(t + 1));
            }
            __syncthreads();
            xz = nxz; xr = nxr; xh = nxh;
        }
    }
}

// ---------------- launcher ----------------
extern "C" void kernel_launch(void* const* d_in, const int* in_sizes, int n_in,
                              void* d_out, int out_size) {
    const float* x  = (const float*)d_in[0];
    const float* W0 = (const float*)d_in[1];
    const float* R0 = (const float*)d_in[2];
    const float* b0 = (const float*)d_in[3];
    const float* W1 = (const float*)d_in[4];
    const float* R1 = (const float*)d_in[5];
    const float* b1 = (const float*)d_in[6];

    float* out  = (float*)d_out;
    float* out1 = out;                               // [64,1024,512]
    float* h0   = out + (size_t)B_ * T_ * U_;        // [64,512]
    float* h1   = h0 + (size_t)B_ * U_;              // [64,512]

    cudaFuncSetAttribute(gru_rec, cudaFuncAttributeMaxDynamicSharedMemorySize,
                         SMEM_REC_BYTES);
    cudaFuncSetAttribute(gemm_mma, cudaFuncAttributeMaxDynamicSharedMemorySize,
                         SMEM_GEMM);

    prep_weights<<<NC_ * U_ / 256, 256>>>(W0, W1, R0, R1);   // 0
    split_x<<<4096, 256>>>(x);                               // 1
    dim3 g0(12, 512);
    gemm_mma<<<g0, 256, SMEM_GEMM>>>(b0, 0);                 // 2
    gru_rec<<<NREC + NCHASE, 256, SMEM_REC_BYTES>>>(0, b0, nullptr, 1, h0,
                                                    0u, b1);  // 3 -> ncu
    dim3 g1(12, 384);
    gemm_mma<<<g1, 256, SMEM_GEMM>>>(b1, 1);                 // 4
    gru_rec<<<NREC, 256, SMEM_REC_BYTES>>>(1, b1, out1, 0, h1,
                                           32u * (T_ - 1), nullptr);  // 5
}